// round 12
// baseline (speedup 1.0000x reference)
#include <cuda_runtime.h>
#include <cuda_bf16.h>
#include <math.h>
#include <stdint.h>

#define Bb 2
#define Ll 2048
#define Dd 1024
#define LH 8
#define MLEN (Bb * Ll)   // 4096

// ---------------- scratch ----------------
__device__ int8_t g_xqh[MLEN * Dd], g_xql[MLEN * Dd];       // x int16-split planes
__device__ int8_t g_Wt0h[Dd * Dd], g_Wt0l[Dd * Dd];         // Wq^T [N,K]
__device__ int8_t g_Wt1h[Dd * Dd], g_Wt1l[Dd * Dd];         // Wk^T
__device__ int8_t g_Wt2h[Dd * Dd], g_Wt2l[Dd * Dd];         // Wv^T
__device__ uint16_t g_Woh[Dd * Dd], g_Wol[Dd * Dd];         // Wo bf16 split
__device__ uint16_t g_Qh[MLEN * Dd], g_Ql[MLEN * Dd];
__device__ uint16_t g_Kh[MLEN * Dd], g_Kl[MLEN * Dd];
__device__ uint16_t g_Vh[MLEN * Dd], g_Vl[MLEN * Dd];
__device__ uint16_t g_Oh[MLEN * Dd], g_Ol[MLEN * Dd];
__device__ float2 g_bstats[32 * 2048 * 32];
__device__ float2 g_rstats[32 * 2048];
__device__ unsigned g_scaleu[4];   // absmax bits: x, Wq, Wk, Wv

// ---------------- helpers ----------------
__device__ __forceinline__ uint32_t smem_u32(const void* p) {
    return (uint32_t)__cvta_generic_to_shared(p);
}

__device__ __forceinline__ void cp_async16(uint32_t dst, const void* src) {
    asm volatile("cp.async.cg.shared.global [%0], [%1], 16;"
                 :: "r"(dst), "l"(src) : "memory");
}
#define CP_COMMIT() asm volatile("cp.async.commit_group;" ::: "memory")
#define CP_WAIT0()  asm volatile("cp.async.wait_group 0;" ::: "memory")

__device__ __forceinline__ void pack_split2(float x0, float x1, uint32_t& h, uint32_t& l) {
    uint32_t u0 = __float_as_uint(x0), u1 = __float_as_uint(x1);
    h = (u0 >> 16) | (u1 & 0xffff0000u);
    float r0 = x0 - __uint_as_float(u0 & 0xffff0000u);
    float r1 = x1 - __uint_as_float(u1 & 0xffff0000u);
    asm("cvt.rn.bf16x2.f32 %0, %1, %2;" : "=r"(l) : "f"(r1), "f"(r0));
}
__device__ __forceinline__ void split_f4(float4 v, uint2& h, uint2& l) {
    pack_split2(v.x, v.y, h.x, l.x);
    pack_split2(v.z, v.w, h.y, l.y);
}

__device__ __forceinline__ void ldsm_x4(uint32_t addr, uint32_t& r0, uint32_t& r1,
                                        uint32_t& r2, uint32_t& r3) {
    asm volatile("ldmatrix.sync.aligned.m8n8.x4.shared.b16 {%0,%1,%2,%3}, [%4];"
                 : "=r"(r0), "=r"(r1), "=r"(r2), "=r"(r3) : "r"(addr));
}
__device__ __forceinline__ void ldsm_x4_t(uint32_t addr, uint32_t& r0, uint32_t& r1,
                                          uint32_t& r2, uint32_t& r3) {
    asm volatile("ldmatrix.sync.aligned.m8n8.x4.trans.shared.b16 {%0,%1,%2,%3}, [%4];"
                 : "=r"(r0), "=r"(r1), "=r"(r2), "=r"(r3) : "r"(addr));
}

__device__ __forceinline__ void mma_bf16(float* c, const uint32_t* a,
                                         uint32_t b0, uint32_t b1) {
    asm volatile(
        "mma.sync.aligned.m16n8k16.row.col.f32.bf16.bf16.f32 "
        "{%0,%1,%2,%3},{%4,%5,%6,%7},{%8,%9},{%0,%1,%2,%3};"
        : "+f"(c[0]), "+f"(c[1]), "+f"(c[2]), "+f"(c[3])
        : "r"(a[0]), "r"(a[1]), "r"(a[2]), "r"(a[3]), "r"(b0), "r"(b1));
}
__device__ __forceinline__ void mma_s8(int* c, const uint32_t* a,
                                       uint32_t b0, uint32_t b1) {
    asm volatile(
        "mma.sync.aligned.m16n8k32.row.col.s32.s8.s8.s32 "
        "{%0,%1,%2,%3},{%4,%5,%6,%7},{%8,%9},{%0,%1,%2,%3};"
        : "+r"(c[0]), "+r"(c[1]), "+r"(c[2]), "+r"(c[3])
        : "r"(a[0]), "r"(a[1]), "r"(a[2]), "r"(a[3]), "r"(b0), "r"(b1));
}

// int16 fixed-point split: i = rn(x*inv) in [-32512,32512]; i = 256*hi + lo
__device__ __forceinline__ void q16(float x, float inv, int8_t& h, int8_t& l) {
    int i = __float2int_rn(x * inv);
    int hi = (i + 128) >> 8;
    h = (int8_t)hi;
    l = (int8_t)(i - (hi << 8));
}

// ---------------- scale prep ----------------
__global__ void init_scales(unsigned* sc) {
    if (threadIdx.x < 4) sc[threadIdx.x] = 0u;
}

__global__ void absmax_k(const float* __restrict__ x,
                         const float* __restrict__ wq,
                         const float* __restrict__ wk,
                         const float* __restrict__ wv, unsigned* sc) {
    int z = blockIdx.z;
    const float* p = (z == 0) ? x : (z == 1) ? wq : (z == 2) ? wk : wv;
    int n = (z == 0) ? MLEN * Dd : Dd * Dd;
    float m = 0.f;
    for (int i = blockIdx.x * 256 + threadIdx.x; i < n; i += gridDim.x * 256)
        m = fmaxf(m, fabsf(p[i]));
    #pragma unroll
    for (int o = 16; o; o >>= 1) m = fmaxf(m, __shfl_xor_sync(0xffffffffu, m, o));
    __shared__ float sm_[8];
    if ((threadIdx.x & 31) == 0) sm_[threadIdx.x >> 5] = m;
    __syncthreads();
    if (threadIdx.x == 0) {
        float mm = fmaxf(fmaxf(fmaxf(sm_[0], sm_[1]), fmaxf(sm_[2], sm_[3])),
                         fmaxf(fmaxf(sm_[4], sm_[5]), fmaxf(sm_[6], sm_[7])));
        atomicMax(&sc[z], __float_as_uint(fmaxf(mm, 1e-30f)));
    }
}

__global__ void quant_x_k(const float4* __restrict__ x, char4* __restrict__ h,
                          char4* __restrict__ l, const unsigned* __restrict__ sc, int n4) {
    int i = blockIdx.x * 256 + threadIdx.x;
    if (i >= n4) return;
    float inv = 32512.f / __uint_as_float(sc[0]);
    float4 v = x[i];
    int8_t hh[4], ll[4];
    q16(v.x, inv, hh[0], ll[0]);
    q16(v.y, inv, hh[1], ll[1]);
    q16(v.z, inv, hh[2], ll[2]);
    q16(v.w, inv, hh[3], ll[3]);
    h[i] = make_char4(hh[0], hh[1], hh[2], hh[3]);
    l[i] = make_char4(ll[0], ll[1], ll[2], ll[3]);
}

// transpose + quantize: W[K,N] -> Wt[N,K] int8 hi/lo planes
__global__ void quantT_w_k(
    const float* __restrict__ w0, int8_t* t0h, int8_t* t0l,
    const float* __restrict__ w1, int8_t* t1h, int8_t* t1l,
    const float* __restrict__ w2, int8_t* t2h, int8_t* t2l,
    const unsigned* __restrict__ sc)
{
    int z = blockIdx.z;
    const float* W = (z == 0) ? w0 : (z == 1) ? w1 : w2;
    int8_t* Th = (z == 0) ? t0h : (z == 1) ? t1h : t2h;
    int8_t* Tl = (z == 0) ? t0l : (z == 1) ? t1l : t2l;
    float inv = 32512.f / __uint_as_float(sc[1 + z]);

    __shared__ float tile[32][33];
    int kb = blockIdx.y * 32, nb = blockIdx.x * 32;
    int t = threadIdx.x;
    int r = t >> 3, c4 = (t & 7) * 4;
    float4 v = *(const float4*)&W[(size_t)(kb + r) * Dd + nb + c4];
    tile[r][c4 + 0] = v.x; tile[r][c4 + 1] = v.y;
    tile[r][c4 + 2] = v.z; tile[r][c4 + 3] = v.w;
    __syncthreads();
    int orow = t >> 3, oc = (t & 7) * 4;
    int8_t hh[4], ll[4];
    #pragma unroll
    for (int i = 0; i < 4; i++)
        q16(tile[oc + i][orow], inv, hh[i], ll[i]);
    size_t o = (size_t)(nb + orow) * Dd + kb + oc;
    *(char4*)&Th[o] = make_char4(hh[0], hh[1], hh[2], hh[3]);
    *(char4*)&Tl[o] = make_char4(ll[0], ll[1], ll[2], ll[3]);
}

// bf16 split for Wo only
__global__ void split_kernel(const float4* __restrict__ src, uint2* __restrict__ h,
                             uint2* __restrict__ l, int n4) {
    int i = blockIdx.x * 256 + threadIdx.x;
    if (i < n4) {
        uint2 hh, ll;
        split_f4(src[i], hh, ll);
        h[i] = hh;
        l[i] = ll;
    }
}

// ---------------- QKV projection: int16-split IMMA, 128x64 tile, K-chunk 64 ---
// stage (bytes): Ah @0 (128x80), Al @10240, Bh @20480 (64x80), Bl @25600
#define I8STG 30720
#define I8_SMEM (2 * I8STG)

__global__ __launch_bounds__(256, 2) void gemm_i8(
    const int8_t* __restrict__ xh, const int8_t* __restrict__ xl,
    const int8_t* __restrict__ w0h, const int8_t* __restrict__ w0l,
    const float* __restrict__ b0, uint16_t* o0h, uint16_t* o0l,
    const int8_t* __restrict__ w1h, const int8_t* __restrict__ w1l,
    const float* __restrict__ b1, uint16_t* o1h, uint16_t* o1l,
    const int8_t* __restrict__ w2h, const int8_t* __restrict__ w2l,
    const float* __restrict__ b2, uint16_t* o2h, uint16_t* o2l,
    const unsigned* __restrict__ scu)
{
    extern __shared__ __align__(16) uint8_t sm8[];
    int z = blockIdx.z;
    const int8_t* Wh = (z == 0) ? w0h : (z == 1) ? w1h : w2h;
    const int8_t* Wl = (z == 0) ? w0l : (z == 1) ? w1l : w2l;
    const float* bias = (z == 0) ? b0 : (z == 1) ? b1 : b2;
    uint16_t* outH = (z == 0) ? o0h : (z == 1) ? o1h : o2h;
    uint16_t* outL = (z == 0) ? o0l : (z == 1) ? o1l : o2l;

    int tid = threadIdx.x, lane = tid & 31, wid = tid >> 5;
    int rowBase = blockIdx.y * 128, colBase = blockIdx.x * 64;
    int m0 = (wid >> 1) * 32, n0 = (wid & 1) * 32;

    int acc0[2][4][4], acc1[2][4][4];
    #pragma unroll
    for (int i = 0; i < 2; i++)
        #pragma unroll
        for (int j = 0; j < 4; j++)
            #pragma unroll
            for (int q = 0; q < 4; q++) { acc0[i][j][q] = 0; acc1[i][j][q] = 0; }

    uint32_t sb = smem_u32(sm8);
    int arow = tid >> 1, ahalf = (tid & 1) * 32;
    int brow = tid >> 2, bseg = (tid & 3) * 16;
    size_t aBase = (size_t)(rowBase + arow) * Dd;
    size_t bBase = (size_t)(colBase + brow) * Dd;

    // stage chunk k0 into buffer buf
    auto stage = [&](int buf, int k0) {
        uint32_t st = sb + (uint32_t)buf * I8STG;
        uint32_t aO = (uint32_t)(arow * 80 + ahalf);
        cp_async16(st + aO, &xh[aBase + k0 + ahalf]);
        cp_async16(st + aO + 16, &xh[aBase + k0 + ahalf + 16]);
        cp_async16(st + 10240 + aO, &xl[aBase + k0 + ahalf]);
        cp_async16(st + 10240 + aO + 16, &xl[aBase + k0 + ahalf + 16]);
        uint32_t bO = (uint32_t)(brow * 80 + bseg);
        cp_async16(st + 20480 + bO, &Wh[bBase + k0 + bseg]);
        cp_async16(st + 25600 + bO, &Wl[bBase + k0 + bseg]);
    };

    stage(0, 0);
    CP_COMMIT();

    int frow = lane >> 2, fcol = (lane & 3) * 4;
    const int NK = Dd / 64;   // 16
    for (int ks = 0; ks < NK; ks++) {
        int cur = ks & 1;
        CP_WAIT0();
        __syncthreads();
        if (ks + 1 < NK) {
            stage(cur ^ 1, (ks + 1) * 64);
            CP_COMMIT();
        }
        uint32_t st = sb + (uint32_t)cur * I8STG;
        #pragma unroll
        for (int kb = 0; kb < 64; kb += 32) {
            uint32_t ah[2][4], al[2][4];
            #pragma unroll
            for (int i = 0; i < 2; i++) {
                uint32_t base = st + (uint32_t)((m0 + i * 16 + frow) * 80 + fcol + kb);
                ah[i][0] = *(const uint32_t*)(sm8 + (base - sb));
                ah[i][1] = *(const uint32_t*)(sm8 + (base - sb) + 640);
                ah[i][2] = *(const uint32_t*)(sm8 + (base - sb) + 16);
                ah[i][3] = *(const uint32_t*)(sm8 + (base - sb) + 656);
                al[i][0] = *(const uint32_t*)(sm8 + (base - sb) + 10240);
                al[i][1] = *(const uint32_t*)(sm8 + (base - sb) + 10880);
                al[i][2] = *(const uint32_t*)(sm8 + (base - sb) + 10256);
                al[i][3] = *(const uint32_t*)(sm8 + (base - sb) + 10896);
            }
            #pragma unroll
            for (int j = 0; j < 4; j++) {
                uint32_t bo = (uint32_t)cur * I8STG + 20480 +
                              (uint32_t)((n0 + j * 8 + frow) * 80 + fcol + kb);
                uint32_t bh0 = *(const uint32_t*)(sm8 + bo);
                uint32_t bh1 = *(const uint32_t*)(sm8 + bo + 16);
                uint32_t bl0 = *(const uint32_t*)(sm8 + bo + 5120);
                uint32_t bl1 = *(const uint32_t*)(sm8 + bo + 5136);
                #pragma unroll
                for (int i = 0; i < 2; i++) {
                    mma_s8(acc0[i][j], ah[i], bh0, bh1);
                    mma_s8(acc1[i][j], ah[i], bl0, bl1);
                    mma_s8(acc1[i][j], al[i], bh0, bh1);
                }
            }
        }
    }

    float sxm = __uint_as_float(scu[0]);
    float swm = __uint_as_float(scu[1 + z]);
    float ss = (sxm / 32512.f) * (swm / 32512.f);
    float sHH = ss * 65536.f, sX = ss * 256.f;

    int r = lane >> 2, cl2 = (lane & 3) * 2;
    #pragma unroll
    for (int i = 0; i < 2; i++) {
        int row = rowBase + m0 + i * 16 + r;
        #pragma unroll
        for (int j = 0; j < 4; j++) {
            int col = colBase + n0 + j * 8 + cl2;
            float bb0 = bias[col], bb1 = bias[col + 1];
            float v0 = sHH * (float)acc0[i][j][0] + sX * (float)acc1[i][j][0] + bb0;
            float v1 = sHH * (float)acc0[i][j][1] + sX * (float)acc1[i][j][1] + bb1;
            float v2 = sHH * (float)acc0[i][j][2] + sX * (float)acc1[i][j][2] + bb0;
            float v3 = sHH * (float)acc0[i][j][3] + sX * (float)acc1[i][j][3] + bb1;
            uint32_t hh, ll;
            pack_split2(v0, v1, hh, ll);
            *(uint32_t*)&outH[(size_t)row * Dd + col] = hh;
            *(uint32_t*)&outL[(size_t)row * Dd + col] = ll;
            pack_split2(v2, v3, hh, ll);
            *(uint32_t*)&outH[(size_t)(row + 8) * Dd + col] = hh;
            *(uint32_t*)&outL[(size_t)(row + 8) * Dd + col] = ll;
        }
    }
}

// ---------------- out-projection: bf16 3-pass (unchanged, 32-chunk 2-stage) ---
#define GSTG 37888
#define GEMM_SMEM (2 * GSTG)

__device__ __forceinline__ void gemm_stage32(
    const uint16_t* __restrict__ Ah, const uint16_t* __restrict__ Al,
    const uint16_t* __restrict__ Bh, const uint16_t* __restrict__ Bl,
    uint32_t sb, int buf, int k0, size_t aRow, int colBase,
    int arow, int acol, int brow, int bcol)
{
    const int N = 1024;
    uint32_t st = sb + (uint32_t)buf * GSTG;
    uint32_t aO = (uint32_t)(arow * 40 + acol) * 2;
    uint32_t bO = (uint32_t)(brow * 136 + bcol) * 2;
    const uint16_t* ag = &Ah[aRow + k0 + acol];
    const uint16_t* alg = &Al[aRow + k0 + acol];
    cp_async16(st + aO, ag);
    cp_async16(st + aO + 16, ag + 8);
    cp_async16(st + 10240 + aO, alg);
    cp_async16(st + 10240 + aO + 16, alg + 8);
    const uint16_t* bg = &Bh[(size_t)(k0 + brow) * N + colBase + bcol];
    const uint16_t* blg = &Bl[(size_t)(k0 + brow) * N + colBase + bcol];
    cp_async16(st + 20480 + bO, bg);
    cp_async16(st + 20480 + bO + 16, bg + 8);
    cp_async16(st + 29184 + bO, blg);
    cp_async16(st + 29184 + bO + 16, blg + 8);
}

__global__ __launch_bounds__(256, 2) void gemm_out(
    const uint16_t* __restrict__ Ah, const uint16_t* __restrict__ Al,
    const uint16_t* __restrict__ Bh, const uint16_t* __restrict__ Bl,
    const float* __restrict__ bias, float* __restrict__ outF)
{
    extern __shared__ __align__(16) uint8_t dsm8[];
    const int N = 1024, K = 1024;
    int tid = threadIdx.x, lane = tid & 31, wid = tid >> 5;
    int rowBase = blockIdx.y * 128, colBase = blockIdx.x * 128;
    int m0 = (wid >> 1) * 32, n0 = (wid & 1) * 64;

    int arow = tid >> 1, acol = (tid & 1) * 16;
    int brow = tid >> 3, bcol = (tid & 7) * 16;

    float c[2][8][4];
    #pragma unroll
    for (int i = 0; i < 2; i++)
        #pragma unroll
        for (int j = 0; j < 8; j++)
            #pragma unroll
            for (int q = 0; q < 4; q++) c[i][j][q] = 0.f;

    uint32_t sb = smem_u32(dsm8);
    uint32_t aoff = (((m0 + (lane & 15)) * 40) + (lane >> 4) * 8) * 2;
    uint32_t boff = ((((lane & 7) + ((lane >> 3) & 1) * 8) * 136) +
                     n0 + (lane >> 4) * 8) * 2;

    size_t aRow = (size_t)(rowBase + arow) * K;
    const int NK = K / 32;

    gemm_stage32(Ah, Al, Bh, Bl, sb, 0, 0, aRow, colBase, arow, acol, brow, bcol);
    CP_COMMIT();

    for (int ks = 0; ks < NK; ks++) {
        int cur = ks & 1;
        CP_WAIT0();
        __syncthreads();
        if (ks + 1 < NK) {
            gemm_stage32(Ah, Al, Bh, Bl, sb, cur ^ 1, (ks + 1) * 32,
                         aRow, colBase, arow, acol, brow, bcol);
            CP_COMMIT();
        }
        uint32_t st = sb + (uint32_t)cur * GSTG;
        #pragma unroll
        for (int kk = 0; kk < 2; kk++) {
            uint32_t afh[2][4], afl[2][4];
            #pragma unroll
            for (int i = 0; i < 2; i++) {
                ldsm_x4(st + aoff + kk * 32 + i * 1280,
                        afh[i][0], afh[i][1], afh[i][2], afh[i][3]);
                ldsm_x4(st + 10240 + aoff + kk * 32 + i * 1280,
                        afl[i][0], afl[i][1], afl[i][2], afl[i][3]);
            }
            #pragma unroll
            for (int j = 0; j < 4; j++) {
                uint32_t bh0, bh1, bh2, bh3, bl0, bl1, bl2, bl3;
                ldsm_x4_t(st + 20480 + boff + kk * 4352 + j * 32, bh0, bh1, bh2, bh3);
                ldsm_x4_t(st + 29184 + boff + kk * 4352 + j * 32, bl0, bl1, bl2, bl3);
                #pragma unroll
                for (int i = 0; i < 2; i++) {
                    mma_bf16(c[i][2 * j], afh[i], bh0, bh1);
                    mma_bf16(c[i][2 * j], afh[i], bl0, bl1);
                    mma_bf16(c[i][2 * j], afl[i], bh0, bh1);
                    mma_bf16(c[i][2 * j + 1], afh[i], bh2, bh3);
                    mma_bf16(c[i][2 * j + 1], afh[i], bl2, bl3);
                    mma_bf16(c[i][2 * j + 1], afl[i], bh2, bh3);
                }
            }
        }
    }

    int r = lane >> 2, cl2 = (lane & 3) * 2;
    #pragma unroll
    for (int i = 0; i < 2; i++) {
        int row = rowBase + m0 + i * 16 + r;
        #pragma unroll
        for (int j = 0; j < 8; j++) {
            int col = colBase + n0 + j * 8 + cl2;
            float b0 = bias[col], b1 = bias[col + 1];
            *(float2*)&outF[(size_t)row * N + col] =
                make_float2(c[i][j][0] + b0, c[i][j][1] + b1);
            *(float2*)&outF[(size_t)(row + 8) * N + col] =
                make_float2(c[i][j][2] + b0, c[i][j][3] + b1);
        }
    }
}

// ---------------- scores: bf16 3-pass, all K=64 resident, ONE sync -----------
#define SC_SMEM 73728
__global__ __launch_bounds__(256, 2) void scores_mma(
    const uint16_t* __restrict__ Qh, const uint16_t* __restrict__ Ql,
    const uint16_t* __restrict__ Kh, const uint16_t* __restrict__ Kl,
    const float* __restrict__ lsc, const float* __restrict__ gsc,
    float* __restrict__ attnL, float* __restrict__ attnG,
    float2* __restrict__ bstats)
{
    int bh = blockIdx.z;
    int b = bh >> 4, h = bh & 15;
    int rowBase = blockIdx.y * 128, colBase = blockIdx.x * 128;
    bool is_local = (h < LH);
    float* dst = is_local ? attnL + (size_t)(b * LH + h) * Ll * Ll
                          : attnG + (size_t)(b * LH + h - LH) * Ll * Ll;
    int tid = threadIdx.x;

    if (is_local && colBase > rowBase) {
        float4 z4 = make_float4(0.f, 0.f, 0.f, 0.f);
        #pragma unroll
        for (int i = 0; i < 16; i++) {
            int s = tid + i * 256;
            int row = s >> 5, c4 = s & 31;
            __stcs((float4*)&dst[(size_t)(rowBase + row) * Ll + colBase + c4 * 4], z4);
        }
        return;
    }
    bool diag = is_local && (colBase == rowBase);
    float scale = 0.125f * (is_local ? lsc[0] : gsc[0]);

    extern __shared__ __align__(16) uint16_t dsm[];
    uint16_t* sQh = dsm;
    uint16_t* sQl = dsm + 9216;
    uint16_t* sKh = dsm + 18432;
    uint16_t* sKl = dsm + 27648;

    int lane = tid & 31, wid = tid >> 5;
    int m0 = (wid >> 1) * 32, n0 = (wid & 1) * 64;

    #pragma unroll
    for (int i = 0; i < 4; i++) {
        int idx = tid + i * 256;
        int row = idx >> 3, cseg = (idx & 7) * 8;
        size_t gq = (size_t)(b * Ll + rowBase + row) * Dd + h * 64 + cseg;
        size_t gk = (size_t)(b * Ll + colBase + row) * Dd + h * 64 + cseg;
        *(uint4*)&sQh[row * 72 + cseg] = *(const uint4*)&Qh[gq];
        *(uint4*)&sQl[row * 72 + cseg] = *(const uint4*)&Ql[gq];
        *(uint4*)&sKh[row * 72 + cseg] = *(const uint4*)&Kh[gk];
        *(uint4*)&sKl[row * 72 + cseg] = *(const uint4*)&Kl[gk];
    }
    __syncthreads();

    float c[2][8][4];
    #pragma unroll
    for (int i = 0; i < 2; i++)
        #pragma unroll
        for (int j = 0; j < 8; j++)
            #pragma unroll
            for (int q = 0; q < 4; q++) c[i][j][q] = 0.f;

    uint32_t sQhA = smem_u32(sQh), sQlA = smem_u32(sQl);
    uint32_t sKhA = smem_u32(sKh), sKlA = smem_u32(sKl);
    uint32_t aoff = (((m0 + (lane & 15)) * 72) + (lane >> 4) * 8) * 2;
    uint32_t boff = (((n0 + (lane & 7) + (lane >> 4) * 8) * 72) +
                     ((lane >> 3) & 1) * 8) * 2;

    #pragma unroll
    for (int kk = 0; kk < 4; kk++) {
        uint32_t afh[2][4], afl[2][4];
        #pragma unroll
        for (int i = 0; i < 2; i++) {
            ldsm_x4(sQhA + aoff + i * 2304 + kk * 32,
                    afh[i][0], afh[i][1], afh[i][2], afh[i][3]);
            ldsm_x4(sQlA + aoff + i * 2304 + kk * 32,
                    afl[i][0], afl[i][1], afl[i][2], afl[i][3]);
        }
        #pragma unroll
        for (int j = 0; j < 4; j++) {
            uint32_t bh0, bh1, bh2, bh3, bl0, bl1, bl2, bl3;
            ldsm_x4(sKhA + boff + j * 2304 + kk * 32, bh0, bh1, bh2, bh3);
            ldsm_x4(sKlA + boff + j * 2304 + kk * 32, bl0, bl1, bl2, bl3);
            #pragma unroll
            for (int i = 0; i < 2; i++) {
                mma_bf16(c[i][2 * j], afh[i], bh0, bh1);
                mma_bf16(c[i][2 * j], afh[i], bl0, bl1);
                mma_bf16(c[i][2 * j], afl[i], bh0, bh1);
                mma_bf16(c[i][2 * j + 1], afh[i], bh2, bh3);
                mma_bf16(c[i][2 * j + 1], afh[i], bl2, bl3);
                mma_bf16(c[i][2 * j + 1], afl[i], bh2, bh3);
            }
        }
    }

    #pragma unroll
    for (int i = 0; i < 2; i++)
        #pragma unroll
        for (int j = 0; j < 8; j++)
            #pragma unroll
            for (int q = 0; q < 4; q++) c[i][j][q] *= scale;

    int r = lane >> 2, cl2 = (lane & 3) * 2;
    int ntile = (colBase + n0) >> 6;

    if (!diag) {
        #pragma unroll
        for (int i = 0; i < 2; i++) {
            #pragma unroll
            for (int half = 0; half < 2; half++) {
                int row = rowBase + m0 + i * 16 + r + half * 8;
                float m = -INFINITY;
                #pragma unroll
                for (int j = 0; j < 8; j++)
                    m = fmaxf(m, fmaxf(c[i][j][half * 2], c[i][j][half * 2 + 1]));
                m = fmaxf(m, __shfl_xor_sync(0xffffffffu, m, 1));
                m = fmaxf(m, __shfl_xor_sync(0xffffffffu, m, 2));
                float s = 0.f;
                #pragma unroll
                for (int j = 0; j < 8; j++) {
                    s += __expf(c[i][j][half * 2] - m);
                    s += __expf(c[i][j][half * 2 + 1] - m);
                }
                s += __shfl_xor_sync(0xffffffffu, s, 1);
                s += __shfl_xor_sync(0xffffffffu, s, 2);
                if ((lane & 3) == 0)
                    bstats[((size_t)bh * 2048 + row) * 32 + ntile] = make_float2(m, s);
                #pragma unroll
                for (int j = 0; j < 8; j++)
                    __stcs((float2*)&dst[(size_t)row * Ll + colBase + n0 + j * 8 + cl2],
                           make_float2(c[i][j][half * 2], c[i][j][half * 2 + 1]));
            }
        }
    } else {
        #pragma unroll
        for (int i = 0; i < 2; i++) {
            #pragma unroll
            for (int half = 0; half < 2; half++) {
                int row = rowBase + m0 + i * 16 + r + half * 8;
                float m = -INFINITY;
                #pragma unroll
                for (int j = 0; j < 8; j++) {
                    int col = colBase + n0 + j * 8 + cl2;
                    float v0 = c[i][j][half * 2], v1 = c[i][j][half * 2 + 1];
                    m = fmaxf(m, (col <= row) ? v0 : -INFINITY);
                    m = fmaxf(m, (col + 1 <= row) ? v1 : -INFINITY);
                }
                m = fmaxf(m, __shfl_xor_sync(0xffffffffu, m, 1));
                m = fmaxf(m, __shfl_xor_sync(0xffffffffu, m, 2));
                float s = 0.f;
                if (m > -1e30f) {
                    #pragma unroll
                    for (int j = 0; j < 8; j++) {
                        int col = colBase + n0 + j * 8 + cl2;
                        s += (col <= row) ? __expf(c[i][j][half * 2] - m) : 0.f;
                        s += (col + 1 <= row) ? __expf(c[i][j][half * 2 + 1] - m) : 0.f;
                    }
                }
                s += __shfl_xor_sync(0xffffffffu, s, 1);
                s += __shfl_xor_sync(0xffffffffu, s, 2);
                if ((lane & 3) == 0)
                    bstats[((size_t)bh * 2048 + row) * 32 + ntile] = make_float2(m, s);
                #pragma unroll
                for (int j = 0; j < 8; j++) {
                    int col = colBase + n0 + j * 8 + cl2;
                    float v0 = (col <= row) ? c[i][j][half * 2] : 0.f;
                    float v1 = (col + 1 <= row) ? c[i][j][half * 2 + 1] : 0.f;
                    __stcs((float2*)&dst[(size_t)row * Ll + col], make_float2(v0, v1));
                }
            }
        }
    }
}

// ---------------- reduce partial stats -> per-row (max, 1/Z) ----------------
__global__ void reduce_stats(const float2* __restrict__ bst, float2* __restrict__ rst) {
    int idx = blockIdx.x * 256 + threadIdx.x;
    int bh = idx >> 11, row = idx & 2047;
    bool is_local = (bh & 15) < LH;
    int jmax = is_local ? (row >> 6) : 31;
    const float2* p = &bst[(size_t)idx * 32];
    float m = -INFINITY;
    for (int j = 0; j <= jmax; j++) m = fmaxf(m, p[j].x);
    float Z = 0.f;
    for (int j = 0; j <= jmax; j++) {
        float2 v = p[j];
        if (v.x > -1e30f) Z += v.y * __expf(v.x - m);
    }
    rst[idx] = make_float2(m, 1.f / Z);
}

// ---------------- AV: chunk=32, cp.async pipelined rawS + V, LPT order --------
#define AV_SMEM 75776

__device__ __forceinline__ void av_prefetch(
    uint32_t sb, int buf, int k0,
    const float* __restrict__ P, const uint16_t* __restrict__ Vh,
    const uint16_t* __restrict__ Vl, size_t vB,
    int rowG, int row, int cs, int krow, int cseg)
{
    #pragma unroll
    for (int g = 0; g < 4; g++)
        cp_async16(sb + buf * 18432 + (row * 36 + cs + g * 4) * 4,
                   &P[(size_t)rowG * Ll + k0 + cs + g * 4]);
    uint32_t vdst = sb + 57344 + buf * 9216 + (krow * 72 + cseg) * 2;
    cp_async16(vdst, &Vh[vB + (size_t)(k0 + krow) * Dd + cseg]);
    cp_async16(vdst + 4608, &Vl[vB + (size_t)(k0 + krow) * Dd + cseg]);
}

__global__ __launch_bounds__(256, 2) void av_mma(
    float* attnL, float* attnG,
    const uint16_t* __restrict__ Vh, const uint16_t* __restrict__ Vl,
    const float2* __restrict__ rst,
    uint16_t* __restrict__ Oh, uint16_t* __restrict__ Ol)
{
    extern __shared__ __align__(16) uint8_t avs[];
    uint32_t sb = smem_u32(avs);

    // LPT remap: heavy CTAs (global heads) first, then local by descending row
    int lin = blockIdx.y * 16 + blockIdx.x;
    int bh, rowIdx;
    if (lin < 256) {
        bh = ((lin >> 7) << 4) + 8 + ((lin >> 4) & 7);
        rowIdx = lin & 15;
    } else {
        int loc = lin - 256;
        rowIdx = 15 - (loc >> 4);
        int sub = loc & 15;
        bh = ((sub >> 3) << 4) + (sub & 7);
    }
    int b = bh >> 4, h = bh & 15;
    int rowBase = rowIdx * 128;
    bool is_local = (h < LH);

    float* P = is_local ? attnL + (size_t)(b * LH + h) * Ll * Ll
                        : attnG + (size_t)(b * LH + h - LH) * Ll * Ll;
    int NK = (is_local ? (rowBase + 128) : Ll) / 32;
    int maskC = is_local ? (rowBase >> 5) : (1 << 30);

    int tid = threadIdx.x, lane = tid & 31, wid = tid >> 5;
    int m0 = (wid >> 1) * 32, n0 = (wid & 1) * 32;

    int row = tid >> 1, cs = (tid & 1) * 16;
    int rowG = rowBase + row;
    float2 st = rst[(size_t)bh * 2048 + rowG];
    int krow = tid >> 3, cseg = (tid & 7) * 8;
    size_t vB = (size_t)(b * Ll) * Dd + h * 64;

    float c[2][4][4];
    #pragma unroll
    for (int i = 0; i < 2; i++)
        #pragma unroll
        for (int j = 0; j < 4; j++)
            #pragma unroll
            for (int q = 0; q < 4; q++) c[i][j][q] = 0.f;

    uint32_t aoff = (((m0 + (lane & 15)) * 40) + (lane >> 4) * 8) * 2;
    uint32_t boff = ((((lane & 7) + ((lane >> 3) & 1) * 8) * 72) +
                     n0 + (lane >> 4) * 8) * 2;

    uint16_t* AhS = (uint16_t*)(avs + 36864);
    uint16_t* AlS = (uint16_t*)(avs + 47104);

    av_prefetch(sb, 0, 0, P, Vh, Vl, vB, rowG, row, cs, krow, cseg);
    CP_COMMIT();

    for (int ck = 0; ck < NK; ck++) {
        int cur = ck & 1;
        int k0 = ck * 32;
        CP_WAIT0();
        __syncthreads();

        {
            const float* rawS = (const float*)(avs + cur * 18432);
            bool needMask = (ck >= maskC);
            float4 p[4];
            #pragma unroll
            for (int g = 0; g < 4; g++) {
                float4 v = *(const float4*)&rawS[row * 36 + cs + g * 4];
                if (!needMask) {
                    p[g].x = __expf(v.x - st.x) * st.y;
                    p[g].y = __expf(v.y - st.x) * st.y;
                    p[g].z = __expf(v.z - st.x) * st.y;
                    p[g].w = __expf(v.w - st.x) * st.y;
                } else {
                    int c0 = k0 + cs + g * 4;
                    p[g].x = (c0 + 0 <= rowG) ? __expf(v.x - st.x) * st.y : 0.f;
                    p[g].y = (c0 + 1 <= rowG) ? __expf(v.y - st.x) * st.y : 0.f;
                    p[g].z = (c0 + 2 <= rowG) ? __expf(v.z - st.x) * st.y : 0.f;
                    p[g].w = (c0 + 3 <= rowG) ? __expf(v.w - st.x) * st.y : 0.f;
                }
                __stcs((float4*)&P[(size_t)rowG * Ll + k0 + cs + g * 4], p[g]);
            }
            uint2 h0, l0, h1, l1, h2, l2, h3, l3;
            split_f4(p[0], h0, l0);
            split_f4(p[1], h1, l1);
            split_f4(p[2], h2, l2);
            split_f4(p[3], h3, l3);
            *(uint4*)&AhS[row * 40 + cs] = make_uint4(h0.x, h0.y, h1.x, h1.y);
            *(uint4*)&AhS[row * 40 + cs + 8] = make_uint4(h2.x, h2.y, h3.x, h3.y);
            *(uint4*)&AlS[row * 40 + cs] = make_uint4(l0.x, l0.y, l1.x, l1.y);
            *(uint4*)&AlS[row * 40 + cs + 8] = make_uint4(l2.x, l2.y, l3.x, l3.y);
        }

        if (ck + 1 < NK) {
            av_prefetch(sb, cur ^ 1, (ck + 1) * 32, P, Vh, Vl, vB,
                        rowG, row, cs, krow, cseg);
            CP_COMMIT();
        }
        __syncthreads();

        uint32_t vhB = sb + 57344 + cur * 9216;
        #pragma unroll
        for (int kk = 0; kk < 2; kk++) {
            uint32_t afh[2][4], afl[2][4];
            #pragma unroll
            for (int i = 0; i < 2; i++) {
                ldsm_x4(sb + 36864 + aoff + kk * 32 + i * 1280,
                        afh[i][0], afh[i][1], afh[i][2], afh[i][3]);
                ldsm_x4(sb + 47104 + aoff + kk * 32 + i * 1280,
                        afl[i][0], afl[i][1], afl[i][2], afl[i][3]);
            }
            #pragma unroll
            for (int j = 0; j < 2; j++) {
                uint32_t bh0, bh1, bh2, bh3, bl0, bl1, bl2, bl3;
                ldsm_x4_t(vhB + boff + kk * 2304 + j * 32, bh0, bh1, bh2, bh3);
                ldsm_x4_t(vhB + 4608 + boff + kk * 2304 + j * 32, bl0, bl1, bl2, bl3);
                #pragma unroll
                for (int i = 0; i < 2; i++) {
                    mma_bf16(c[i][2 * j], afh[i], bh0, bh1);
                    mma_bf16(c[i][2 * j], afh[i], bl0, bl1);
                    mma_bf16(c[i][2 * j], afl[i], bh0, bh1);
                    mma_bf16(c[i][2 * j + 1], afh[i], bh2, bh3);
                    mma_bf16(c[i][2 * j + 1], afh[i], bl2, bl3);
                    mma_bf16(c[i][2 * j + 1], afl[i], bh2, bh3);
                }
            }
        }
    }

    int r = lane >> 2, cl2 = (lane & 3) * 2;
    #pragma unroll
    for (int i = 0; i < 2; i++) {
        int orow = rowBase + m0 + i * 16 + r;
        #pragma unroll
        for (int j = 0; j < 4; j++) {
            int col = n0 + j * 8 + cl2;
            size_t off0 = (size_t)(b * Ll + orow) * Dd + h * 64 + col;
            size_t off1 = (size_t)(b * Ll + orow + 8) * Dd + h * 64 + col;
            uint32_t hh, ll;
            pack_split2(c[i][j][0], c[i][j][1], hh, ll);
            *(uint32_t*)&Oh[off0] = hh;
            *(uint32_t*)&Ol[off0] = ll;
            pack_split2(c[i][j][2], c[i][j][3], hh, ll);
            *(uint32_t*)&Oh[off1] = hh;
            *(uint32_t*)&Ol[off1] = ll;
        }
    }
}

// ---------------- launch ----------------
extern "C" void kernel_launch(void* const* d_in, const int* in_sizes, int n_in,
                              void* d_out, int out_size)
{
    const float* x   = (const float*)d_in[0];
    const float* Wq  = (const float*)d_in[1];
    const float* bq  = (const float*)d_in[2];
    const float* Wk  = (const float*)d_in[3];
    const float* bk  = (const float*)d_in[4];
    const float* Wv  = (const float*)d_in[5];
    const float* bv  = (const float*)d_in[6];
    const float* Wo  = (const float*)d_in[7];
    const float* bo  = (const float*)d_in[8];
    const float* lsc = (const float*)d_in[9];
    const float* gsc = (const float*)d_in[10];

    float* out   = (float*)d_out;
    float* attnL = out + (size_t)MLEN * Dd;
    float* attnG = attnL + (size_t)Bb * LH * Ll * Ll;

    int8_t *xqh, *xql, *w0h, *w0l, *w1h, *w1l, *w2h, *w2l;
    uint16_t *Woh, *Wol, *Qh, *Ql, *Kh, *Kl, *Vh, *Vl, *Ohp, *Olp;
    float2 *bst, *rstp;
    unsigned* scu;
    cudaGetSymbolAddress((void**)&xqh, g_xqh);  cudaGetSymbolAddress((void**)&xql, g_xql);
    cudaGetSymbolAddress((void**)&w0h, g_Wt0h); cudaGetSymbolAddress((void**)&w0l, g_Wt0l);
    cudaGetSymbolAddress((void**)&w1h, g_Wt1h); cudaGetSymbolAddress((void**)&w1l, g_Wt1l);
    cudaGetSymbolAddress((void**)&w2h, g_Wt2h); cudaGetSymbolAddress((void**)&w2l, g_Wt2l);
    cudaGetSymbolAddress((void**)&Woh, g_Woh);  cudaGetSymbolAddress((void**)&Wol, g_Wol);
    cudaGetSymbolAddress((void**)&Qh, g_Qh);    cudaGetSymbolAddress((void**)&Ql, g_Ql);
    cudaGetSymbolAddress((void**)&Kh, g_Kh);    cudaGetSymbolAddress((void**)&Kl, g_Kl);
    cudaGetSymbolAddress((void**)&Vh, g_Vh);    cudaGetSymbolAddress((void**)&Vl, g_Vl);
    cudaGetSymbolAddress((void**)&Ohp, g_Oh);   cudaGetSymbolAddress((void**)&Olp, g_Ol);
    cudaGetSymbolAddress((void**)&bst, g_bstats);
    cudaGetSymbolAddress((void**)&rstp, g_rstats);
    cudaGetSymbolAddress((void**)&scu, g_scaleu);

    cudaFuncSetAttribute(scores_mma, cudaFuncAttributeMaxDynamicSharedMemorySize, SC_SMEM);
    cudaFuncSetAttribute(av_mma, cudaFuncAttributeMaxDynamicSharedMemorySize, AV_SMEM);
    cudaFuncSetAttribute(gemm_i8, cudaFuncAttributeMaxDynamicSharedMemorySize, I8_SMEM);
    cudaFuncSetAttribute(gemm_out, cudaFuncAttributeMaxDynamicSharedMemorySize, GEMM_SMEM);

    int nx4 = MLEN * Dd / 4;
    int nw4 = Dd * Dd / 4;

    init_scales<<<1, 32>>>(scu);
    absmax_k<<<dim3(512, 1, 4), 256>>>(x, Wq, Wk, Wv, scu);
    quant_x_k<<<nx4 / 256, 256>>>((const float4*)x, (char4*)xqh, (char4*)xql, scu, nx4);
    quantT_w_k<<<dim3(32, 32, 3), 256>>>(Wq, w0h, w0l, Wk, w1h, w1l, Wv, w2h, w2l, scu);
    split_kernel<<<nw4 / 256, 256>>>((const float4*)Wo, (uint2*)Woh, (uint2*)Wol, nw4);

    gemm_i8<<<dim3(16, 32, 3), 256, I8_SMEM>>>(xqh, xql,
        w0h, w0l, bq, Qh, Ql,
        w1h, w1l, bk, Kh, Kl,
        w2h, w2l, bv, Vh, Vl, scu);

    scores_mma<<<dim3(16, 16, 32), 256, SC_SMEM>>>(Qh, Ql, Kh, Kl, lsc, gsc,
                                                   attnL, attnG, bst);
    reduce_stats<<<256, 256>>>(bst, rstp);
    av_mma<<<dim3(16, 32), 256, AV_SMEM>>>(attnL, attnG, Vh, Vl, rstp, Ohp, Olp);

    gemm_out<<<dim3(8, 32), 256, GEMM_SMEM>>>(Ohp, Olp, Woh, Wol, bo, out);
}

// round 13
// speedup vs baseline: 1.4321x; 1.4321x over previous
#include <cuda_runtime.h>
#include <cuda_bf16.h>
#include <math.h>
#include <stdint.h>

#define Bb 2
#define Ll 2048
#define Dd 1024
#define LH 8
#define MLEN (Bb * Ll)   // 4096

// ---------------- scratch ----------------
__device__ uint16_t g_xh[MLEN * Dd], g_xl[MLEN * Dd];
__device__ uint16_t g_Wqh[Dd * Dd], g_Wql[Dd * Dd];
__device__ uint16_t g_Wkh[Dd * Dd], g_Wkl[Dd * Dd];
__device__ uint16_t g_Wvh[Dd * Dd], g_Wvl[Dd * Dd];
__device__ uint16_t g_Woh[Dd * Dd], g_Wol[Dd * Dd];
__device__ uint16_t g_Qh[MLEN * Dd], g_Ql[MLEN * Dd];
__device__ uint16_t g_Kh[MLEN * Dd], g_Kl[MLEN * Dd];
__device__ uint16_t g_Vh[MLEN * Dd], g_Vl[MLEN * Dd];
__device__ uint16_t g_Oh[MLEN * Dd], g_Ol[MLEN * Dd];
__device__ float2 g_bstats[32 * 2048 * 32];
__device__ float2 g_rstats[32 * 2048];

// ---------------- helpers ----------------
__device__ __forceinline__ uint32_t smem_u32(const void* p) {
    return (uint32_t)__cvta_generic_to_shared(p);
}

__device__ __forceinline__ void cp_async16(uint32_t dst, const void* src) {
    asm volatile("cp.async.cg.shared.global [%0], [%1], 16;"
                 :: "r"(dst), "l"(src) : "memory");
}
#define CP_COMMIT() asm volatile("cp.async.commit_group;" ::: "memory")
#define CP_WAIT0()  asm volatile("cp.async.wait_group 0;" ::: "memory")
#define CP_WAIT1()  asm volatile("cp.async.wait_group 1;" ::: "memory")

__device__ __forceinline__ void pack_split2(float x0, float x1, uint32_t& h, uint32_t& l) {
    uint32_t u0 = __float_as_uint(x0), u1 = __float_as_uint(x1);
    h = (u0 >> 16) | (u1 & 0xffff0000u);
    float r0 = x0 - __uint_as_float(u0 & 0xffff0000u);
    float r1 = x1 - __uint_as_float(u1 & 0xffff0000u);
    asm("cvt.rn.bf16x2.f32 %0, %1, %2;" : "=r"(l) : "f"(r1), "f"(r0));
}
__device__ __forceinline__ void split_f4(float4 v, uint2& h, uint2& l) {
    pack_split2(v.x, v.y, h.x, l.x);
    pack_split2(v.z, v.w, h.y, l.y);
}

__device__ __forceinline__ void ldsm_x4(uint32_t addr, uint32_t& r0, uint32_t& r1,
                                        uint32_t& r2, uint32_t& r3) {
    asm volatile("ldmatrix.sync.aligned.m8n8.x4.shared.b16 {%0,%1,%2,%3}, [%4];"
                 : "=r"(r0), "=r"(r1), "=r"(r2), "=r"(r3) : "r"(addr));
}
__device__ __forceinline__ void ldsm_x4_t(uint32_t addr, uint32_t& r0, uint32_t& r1,
                                          uint32_t& r2, uint32_t& r3) {
    asm volatile("ldmatrix.sync.aligned.m8n8.x4.trans.shared.b16 {%0,%1,%2,%3}, [%4];"
                 : "=r"(r0), "=r"(r1), "=r"(r2), "=r"(r3) : "r"(addr));
}

__device__ __forceinline__ void mma_bf16(float* c, const uint32_t* a,
                                         uint32_t b0, uint32_t b1) {
    asm volatile(
        "mma.sync.aligned.m16n8k16.row.col.f32.bf16.bf16.f32 "
        "{%0,%1,%2,%3},{%4,%5,%6,%7},{%8,%9},{%0,%1,%2,%3};"
        : "+f"(c[0]), "+f"(c[1]), "+f"(c[2]), "+f"(c[3])
        : "r"(a[0]), "r"(a[1]), "r"(a[2]), "r"(a[3]), "r"(b0), "r"(b1));
}

// ---------------- splits ----------------
__global__ void split_kernel(const float4* __restrict__ src, uint2* __restrict__ h,
                             uint2* __restrict__ l, int n4) {
    int i = blockIdx.x * 256 + threadIdx.x;
    if (i < n4) {
        uint2 hh, ll;
        split_f4(src[i], hh, ll);
        h[i] = hh;
        l[i] = ll;
    }
}

__global__ void split4_kernel(
    const float4* __restrict__ s0, uint2* h0, uint2* l0,
    const float4* __restrict__ s1, uint2* h1, uint2* l1,
    const float4* __restrict__ s2, uint2* h2, uint2* l2,
    const float4* __restrict__ s3, uint2* h3, uint2* l3, int n4)
{
    int z = blockIdx.z;
    const float4* s = (z == 0) ? s0 : (z == 1) ? s1 : (z == 2) ? s2 : s3;
    uint2* h = (z == 0) ? h0 : (z == 1) ? h1 : (z == 2) ? h2 : h3;
    uint2* l = (z == 0) ? l0 : (z == 1) ? l1 : (z == 2) ? l2 : l3;
    int i = blockIdx.x * 256 + threadIdx.x;
    if (i < n4) {
        uint2 hh, ll;
        split_f4(s[i], hh, ll);
        h[i] = hh;
        l[i] = ll;
    }
}

// ---------------- projection GEMM: 128x128, 3-stage cp.async ring -------------
#define PA 24
#define PB2 136
#define GSTAGE 20992   // bytes per stage: Ah 6144 | Al 6144 | Bh 4352 | Bl 4352
#define GEMM_SMEM (3 * GSTAGE)

__device__ __forceinline__ void gemm_stage3(
    const uint16_t* __restrict__ Ah, const uint16_t* __restrict__ Al,
    const uint16_t* __restrict__ Bh, const uint16_t* __restrict__ Bl,
    uint32_t sb, int buf, int k0, size_t aRow, int colBase,
    int ar, int asel, int brow, int bcol)
{
    const int N = 1024;
    uint32_t st = sb + (uint32_t)buf * GSTAGE;
    uint32_t aO = (uint32_t)(ar * PA + asel) * 2;
    uint32_t bO = (uint32_t)(brow * PB2 + bcol) * 2;
    cp_async16(st + aO, &Ah[aRow + k0 + asel]);
    cp_async16(st + 6144 + aO, &Al[aRow + k0 + asel]);
    cp_async16(st + 12288 + bO, &Bh[(size_t)(k0 + brow) * N + colBase + bcol]);
    cp_async16(st + 16640 + bO, &Bl[(size_t)(k0 + brow) * N + colBase + bcol]);
}

__device__ __forceinline__ void gemm_core(
    const uint16_t* __restrict__ Ah, const uint16_t* __restrict__ Al,
    const uint16_t* __restrict__ Bh, const uint16_t* __restrict__ Bl,
    const float* __restrict__ bias,
    uint16_t* __restrict__ outH, uint16_t* __restrict__ outL,
    float* __restrict__ outF, int mode, uint8_t* dsm)
{
    const int N = 1024, K = 1024;
    int tid = threadIdx.x, lane = tid & 31, wid = tid >> 5;
    int rowBase = blockIdx.y * 128, colBase = blockIdx.x * 128;
    int m0 = (wid >> 1) * 32, n0 = (wid & 1) * 64;

    int ar = tid >> 1, asel = (tid & 1) * 8;
    int brow = tid >> 4, bcol = (tid & 15) * 8;

    float c[2][8][4];
    #pragma unroll
    for (int i = 0; i < 2; i++)
        #pragma unroll
        for (int j = 0; j < 8; j++)
            #pragma unroll
            for (int q = 0; q < 4; q++) c[i][j][q] = 0.f;

    uint32_t sb = smem_u32(dsm);
    uint32_t aoff = (((m0 + (lane & 15)) * PA) + (lane >> 4) * 8) * 2;
    uint32_t boff = ((((lane & 7) + ((lane >> 3) & 1) * 8) * PB2) +
                     n0 + (lane >> 4) * 8) * 2;

    size_t aRow = (size_t)(rowBase + ar) * K;
    const int NK = K / 16;

    gemm_stage3(Ah, Al, Bh, Bl, sb, 0, 0, aRow, colBase, ar, asel, brow, bcol);
    CP_COMMIT();
    gemm_stage3(Ah, Al, Bh, Bl, sb, 1, 16, aRow, colBase, ar, asel, brow, bcol);
    CP_COMMIT();

    for (int ks = 0; ks < NK; ks++) {
        CP_WAIT1();
        __syncthreads();
        if (ks + 2 < NK) {
            gemm_stage3(Ah, Al, Bh, Bl, sb, (ks + 2) % 3, (ks + 2) * 16,
                        aRow, colBase, ar, asel, brow, bcol);
            CP_COMMIT();
        }
        uint32_t st = sb + (uint32_t)(ks % 3) * GSTAGE;
        uint32_t afh[2][4], afl[2][4];
        #pragma unroll
        for (int i = 0; i < 2; i++) {
            ldsm_x4(st + aoff + i * 768, afh[i][0], afh[i][1], afh[i][2], afh[i][3]);
            ldsm_x4(st + 6144 + aoff + i * 768, afl[i][0], afl[i][1], afl[i][2], afl[i][3]);
        }
        #pragma unroll
        for (int j = 0; j < 4; j++) {
            uint32_t bh0, bh1, bh2, bh3, bl0, bl1, bl2, bl3;
            ldsm_x4_t(st + 12288 + boff + j * 32, bh0, bh1, bh2, bh3);
            ldsm_x4_t(st + 16640 + boff + j * 32, bl0, bl1, bl2, bl3);
            #pragma unroll
            for (int i = 0; i < 2; i++) {
                mma_bf16(c[i][2 * j], afh[i], bh0, bh1);
                mma_bf16(c[i][2 * j], afh[i], bl0, bl1);
                mma_bf16(c[i][2 * j], afl[i], bh0, bh1);
                mma_bf16(c[i][2 * j + 1], afh[i], bh2, bh3);
                mma_bf16(c[i][2 * j + 1], afh[i], bl2, bl3);
                mma_bf16(c[i][2 * j + 1], afl[i], bh2, bh3);
            }
        }
    }

    int r = lane >> 2, cl2 = (lane & 3) * 2;
    #pragma unroll
    for (int i = 0; i < 2; i++) {
        int row = rowBase + m0 + i * 16 + r;
        #pragma unroll
        for (int j = 0; j < 8; j++) {
            int col = colBase + n0 + j * 8 + cl2;
            float b0 = bias[col], b1 = bias[col + 1];
            if (mode) {
                uint32_t hh, ll;
                pack_split2(c[i][j][0] + b0, c[i][j][1] + b1, hh, ll);
                *(uint32_t*)&outH[(size_t)row * N + col] = hh;
                *(uint32_t*)&outL[(size_t)row * N + col] = ll;
                pack_split2(c[i][j][2] + b0, c[i][j][3] + b1, hh, ll);
                *(uint32_t*)&outH[(size_t)(row + 8) * N + col] = hh;
                *(uint32_t*)&outL[(size_t)(row + 8) * N + col] = ll;
            } else {
                *(float2*)&outF[(size_t)row * N + col] =
                    make_float2(c[i][j][0] + b0, c[i][j][1] + b1);
                *(float2*)&outF[(size_t)(row + 8) * N + col] =
                    make_float2(c[i][j][2] + b0, c[i][j][3] + b1);
            }
        }
    }
}

__global__ __launch_bounds__(256, 2) void gemm_qkv(
    const uint16_t* __restrict__ Ah, const uint16_t* __restrict__ Al,
    const uint16_t* __restrict__ B0h, const uint16_t* __restrict__ B0l,
    const float* __restrict__ bias0, uint16_t* o0h, uint16_t* o0l,
    const uint16_t* __restrict__ B1h, const uint16_t* __restrict__ B1l,
    const float* __restrict__ bias1, uint16_t* o1h, uint16_t* o1l,
    const uint16_t* __restrict__ B2h, const uint16_t* __restrict__ B2l,
    const float* __restrict__ bias2, uint16_t* o2h, uint16_t* o2l)
{
    extern __shared__ __align__(16) uint8_t dsm8[];
    int z = blockIdx.z;
    const uint16_t* Bh = (z == 0) ? B0h : (z == 1) ? B1h : B2h;
    const uint16_t* Bl = (z == 0) ? B0l : (z == 1) ? B1l : B2l;
    const float* bias  = (z == 0) ? bias0 : (z == 1) ? bias1 : bias2;
    uint16_t* outH     = (z == 0) ? o0h : (z == 1) ? o1h : o2h;
    uint16_t* outL     = (z == 0) ? o0l : (z == 1) ? o1l : o2l;
    gemm_core(Ah, Al, Bh, Bl, bias, outH, outL, nullptr, 1, dsm8);
}

__global__ __launch_bounds__(256, 2) void gemm_out(
    const uint16_t* __restrict__ Ah, const uint16_t* __restrict__ Al,
    const uint16_t* __restrict__ Bh, const uint16_t* __restrict__ Bl,
    const float* __restrict__ bias, float* __restrict__ outF)
{
    extern __shared__ __align__(16) uint8_t dsm8[];
    gemm_core(Ah, Al, Bh, Bl, bias, nullptr, nullptr, outF, 0, dsm8);
}

// ---------------- scores: all K=64 resident, ONE sync -------------------------
#define SC_SMEM 73728
__global__ __launch_bounds__(256, 2) void scores_mma(
    const uint16_t* __restrict__ Qh, const uint16_t* __restrict__ Ql,
    const uint16_t* __restrict__ Kh, const uint16_t* __restrict__ Kl,
    const float* __restrict__ lsc, const float* __restrict__ gsc,
    float* __restrict__ attnL, float* __restrict__ attnG,
    float2* __restrict__ bstats)
{
    int bh = blockIdx.z;
    int b = bh >> 4, h = bh & 15;
    int rowBase = blockIdx.y * 128, colBase = blockIdx.x * 128;
    bool is_local = (h < LH);
    float* dst = is_local ? attnL + (size_t)(b * LH + h) * Ll * Ll
                          : attnG + (size_t)(b * LH + h - LH) * Ll * Ll;
    int tid = threadIdx.x;

    if (is_local && colBase > rowBase) {
        float4 z4 = make_float4(0.f, 0.f, 0.f, 0.f);
        #pragma unroll
        for (int i = 0; i < 16; i++) {
            int s = tid + i * 256;
            int row = s >> 5, c4 = s & 31;
            __stcs((float4*)&dst[(size_t)(rowBase + row) * Ll + colBase + c4 * 4], z4);
        }
        return;
    }
    bool diag = is_local && (colBase == rowBase);
    float scale = 0.125f * (is_local ? lsc[0] : gsc[0]);

    extern __shared__ __align__(16) uint16_t dsm[];
    uint16_t* sQh = dsm;
    uint16_t* sQl = dsm + 9216;
    uint16_t* sKh = dsm + 18432;
    uint16_t* sKl = dsm + 27648;

    int lane = tid & 31, wid = tid >> 5;
    int m0 = (wid >> 1) * 32, n0 = (wid & 1) * 64;

    #pragma unroll
    for (int i = 0; i < 4; i++) {
        int idx = tid + i * 256;
        int row = idx >> 3, cseg = (idx & 7) * 8;
        size_t gq = (size_t)(b * Ll + rowBase + row) * Dd + h * 64 + cseg;
        size_t gk = (size_t)(b * Ll + colBase + row) * Dd + h * 64 + cseg;
        *(uint4*)&sQh[row * 72 + cseg] = *(const uint4*)&Qh[gq];
        *(uint4*)&sQl[row * 72 + cseg] = *(const uint4*)&Ql[gq];
        *(uint4*)&sKh[row * 72 + cseg] = *(const uint4*)&Kh[gk];
        *(uint4*)&sKl[row * 72 + cseg] = *(const uint4*)&Kl[gk];
    }
    __syncthreads();

    float c[2][8][4];
    #pragma unroll
    for (int i = 0; i < 2; i++)
        #pragma unroll
        for (int j = 0; j < 8; j++)
            #pragma unroll
            for (int q = 0; q < 4; q++) c[i][j][q] = 0.f;

    uint32_t sQhA = smem_u32(sQh), sQlA = smem_u32(sQl);
    uint32_t sKhA = smem_u32(sKh), sKlA = smem_u32(sKl);
    uint32_t aoff = (((m0 + (lane & 15)) * 72) + (lane >> 4) * 8) * 2;
    uint32_t boff = (((n0 + (lane & 7) + (lane >> 4) * 8) * 72) +
                     ((lane >> 3) & 1) * 8) * 2;

    #pragma unroll
    for (int kk = 0; kk < 4; kk++) {
        uint32_t afh[2][4], afl[2][4];
        #pragma unroll
        for (int i = 0; i < 2; i++) {
            ldsm_x4(sQhA + aoff + i * 2304 + kk * 32,
                    afh[i][0], afh[i][1], afh[i][2], afh[i][3]);
            ldsm_x4(sQlA + aoff + i * 2304 + kk * 32,
                    afl[i][0], afl[i][1], afl[i][2], afl[i][3]);
        }
        #pragma unroll
        for (int j = 0; j < 4; j++) {
            uint32_t bh0, bh1, bh2, bh3, bl0, bl1, bl2, bl3;
            ldsm_x4(sKhA + boff + j * 2304 + kk * 32, bh0, bh1, bh2, bh3);
            ldsm_x4(sKlA + boff + j * 2304 + kk * 32, bl0, bl1, bl2, bl3);
            #pragma unroll
            for (int i = 0; i < 2; i++) {
                mma_bf16(c[i][2 * j], afh[i], bh0, bh1);
                mma_bf16(c[i][2 * j], afh[i], bl0, bl1);
                mma_bf16(c[i][2 * j], afl[i], bh0, bh1);
                mma_bf16(c[i][2 * j + 1], afh[i], bh2, bh3);
                mma_bf16(c[i][2 * j + 1], afh[i], bl2, bl3);
                mma_bf16(c[i][2 * j + 1], afl[i], bh2, bh3);
            }
        }
    }

    #pragma unroll
    for (int i = 0; i < 2; i++)
        #pragma unroll
        for (int j = 0; j < 8; j++)
            #pragma unroll
            for (int q = 0; q < 4; q++) c[i][j][q] *= scale;

    int r = lane >> 2, cl2 = (lane & 3) * 2;
    int ntile = (colBase + n0) >> 6;

    if (!diag) {
        #pragma unroll
        for (int i = 0; i < 2; i++) {
            #pragma unroll
            for (int half = 0; half < 2; half++) {
                int row = rowBase + m0 + i * 16 + r + half * 8;
                float m = -INFINITY;
                #pragma unroll
                for (int j = 0; j < 8; j++)
                    m = fmaxf(m, fmaxf(c[i][j][half * 2], c[i][j][half * 2 + 1]));
                m = fmaxf(m, __shfl_xor_sync(0xffffffffu, m, 1));
                m = fmaxf(m, __shfl_xor_sync(0xffffffffu, m, 2));
                float s = 0.f;
                #pragma unroll
                for (int j = 0; j < 8; j++) {
                    s += __expf(c[i][j][half * 2] - m);
                    s += __expf(c[i][j][half * 2 + 1] - m);
                }
                s += __shfl_xor_sync(0xffffffffu, s, 1);
                s += __shfl_xor_sync(0xffffffffu, s, 2);
                if ((lane & 3) == 0)
                    bstats[((size_t)bh * 2048 + row) * 32 + ntile] = make_float2(m, s);
                #pragma unroll
                for (int j = 0; j < 8; j++)
                    __stcs((float2*)&dst[(size_t)row * Ll + colBase + n0 + j * 8 + cl2],
                           make_float2(c[i][j][half * 2], c[i][j][half * 2 + 1]));
            }
        }
    } else {
        #pragma unroll
        for (int i = 0; i < 2; i++) {
            #pragma unroll
            for (int half = 0; half < 2; half++) {
                int row = rowBase + m0 + i * 16 + r + half * 8;
                float m = -INFINITY;
                #pragma unroll
                for (int j = 0; j < 8; j++) {
                    int col = colBase + n0 + j * 8 + cl2;
                    float v0 = c[i][j][half * 2], v1 = c[i][j][half * 2 + 1];
                    m = fmaxf(m, (col <= row) ? v0 : -INFINITY);
                    m = fmaxf(m, (col + 1 <= row) ? v1 : -INFINITY);
                }
                m = fmaxf(m, __shfl_xor_sync(0xffffffffu, m, 1));
                m = fmaxf(m, __shfl_xor_sync(0xffffffffu, m, 2));
                float s = 0.f;
                if (m > -1e30f) {
                    #pragma unroll
                    for (int j = 0; j < 8; j++) {
                        int col = colBase + n0 + j * 8 + cl2;
                        s += (col <= row) ? __expf(c[i][j][half * 2] - m) : 0.f;
                        s += (col + 1 <= row) ? __expf(c[i][j][half * 2 + 1] - m) : 0.f;
                    }
                }
                s += __shfl_xor_sync(0xffffffffu, s, 1);
                s += __shfl_xor_sync(0xffffffffu, s, 2);
                if ((lane & 3) == 0)
                    bstats[((size_t)bh * 2048 + row) * 32 + ntile] = make_float2(m, s);
                #pragma unroll
                for (int j = 0; j < 8; j++) {
                    int col = colBase + n0 + j * 8 + cl2;
                    float v0 = (col <= row) ? c[i][j][half * 2] : 0.f;
                    float v1 = (col + 1 <= row) ? c[i][j][half * 2 + 1] : 0.f;
                    __stcs((float2*)&dst[(size_t)row * Ll + col], make_float2(v0, v1));
                }
            }
        }
    }
}

// ---------------- reduce partial stats -> per-row (max, 1/Z) ----------------
__global__ void reduce_stats(const float2* __restrict__ bst, float2* __restrict__ rst) {
    int idx = blockIdx.x * 256 + threadIdx.x;
    int bh = idx >> 11, row = idx & 2047;
    bool is_local = (bh & 15) < LH;
    int jmax = is_local ? (row >> 6) : 31;
    const float2* p = &bst[(size_t)idx * 32];
    float m = -INFINITY;
    for (int j = 0; j <= jmax; j++) m = fmaxf(m, p[j].x);
    float Z = 0.f;
    for (int j = 0; j <= jmax; j++) {
        float2 v = p[j];
        if (v.x > -1e30f) Z += v.y * __expf(v.x - m);
    }
    rst[idx] = make_float2(m, 1.f / Z);
}

// ---------------- AV: chunk=32, cp.async pipelined rawS + V, LPT order --------
#define AV_SMEM 75776

__device__ __forceinline__ void av_prefetch(
    uint32_t sb, int buf, int k0,
    const float* __restrict__ P, const uint16_t* __restrict__ Vh,
    const uint16_t* __restrict__ Vl, size_t vB,
    int rowG, int row, int cs, int krow, int cseg)
{
    #pragma unroll
    for (int g = 0; g < 4; g++)
        cp_async16(sb + buf * 18432 + (row * 36 + cs + g * 4) * 4,
                   &P[(size_t)rowG * Ll + k0 + cs + g * 4]);
    uint32_t vdst = sb + 57344 + buf * 9216 + (krow * 72 + cseg) * 2;
    cp_async16(vdst, &Vh[vB + (size_t)(k0 + krow) * Dd + cseg]);
    cp_async16(vdst + 4608, &Vl[vB + (size_t)(k0 + krow) * Dd + cseg]);
}

__global__ __launch_bounds__(256, 2) void av_mma(
    float* attnL, float* attnG,
    const uint16_t* __restrict__ Vh, const uint16_t* __restrict__ Vl,
    const float2* __restrict__ rst,
    uint16_t* __restrict__ Oh, uint16_t* __restrict__ Ol)
{
    extern __shared__ __align__(16) uint8_t avs[];
    uint32_t sb = smem_u32(avs);

    // LPT remap: heavy CTAs (global heads) first, then local by descending row
    int lin = blockIdx.y * 16 + blockIdx.x;
    int bh, rowIdx;
    if (lin < 256) {
        bh = ((lin >> 7) << 4) + 8 + ((lin >> 4) & 7);
        rowIdx = lin & 15;
    } else {
        int loc = lin - 256;
        rowIdx = 15 - (loc >> 4);
        int sub = loc & 15;
        bh = ((sub >> 3) << 4) + (sub & 7);
    }
    int b = bh >> 4, h = bh & 15;
    int rowBase = rowIdx * 128;
    bool is_local = (h < LH);

    float* P = is_local ? attnL + (size_t)(b * LH + h) * Ll * Ll
                        : attnG + (size_t)(b * LH + h - LH) * Ll * Ll;
    int NK = (is_local ? (rowBase + 128) : Ll) / 32;
    int maskC = is_local ? (rowBase >> 5) : (1 << 30);

    int tid = threadIdx.x, lane = tid & 31, wid = tid >> 5;
    int m0 = (wid >> 1) * 32, n0 = (wid & 1) * 32;

    int row = tid >> 1, cs = (tid & 1) * 16;
    int rowG = rowBase + row;
    float2 st = rst[(size_t)bh * 2048 + rowG];
    int krow = tid >> 3, cseg = (tid & 7) * 8;
    size_t vB = (size_t)(b * Ll) * Dd + h * 64;

    float c[2][4][4];
    #pragma unroll
    for (int i = 0; i < 2; i++)
        #pragma unroll
        for (int j = 0; j < 4; j++)
            #pragma unroll
            for (int q = 0; q < 4; q++) c[i][j][q] = 0.f;

    uint32_t aoff = (((m0 + (lane & 15)) * 40) + (lane >> 4) * 8) * 2;
    uint32_t boff = ((((lane & 7) + ((lane >> 3) & 1) * 8) * 72) +
                     n0 + (lane >> 4) * 8) * 2;

    uint16_t* AhS = (uint16_t*)(avs + 36864);
    uint16_t* AlS = (uint16_t*)(avs + 47104);

    av_prefetch(sb, 0, 0, P, Vh, Vl, vB, rowG, row, cs, krow, cseg);
    CP_COMMIT();

    for (int ck = 0; ck < NK; ck++) {
        int cur = ck & 1;
        int k0 = ck * 32;
        CP_WAIT0();
        __syncthreads();

        {
            const float* rawS = (const float*)(avs + cur * 18432);
            bool needMask = (ck >= maskC);
            float4 p[4];
            #pragma unroll
            for (int g = 0; g < 4; g++) {
                float4 v = *(const float4*)&rawS[row * 36 + cs + g * 4];
                if (!needMask) {
                    p[g].x = __expf(v.x - st.x) * st.y;
                    p[g].y = __expf(v.y - st.x) * st.y;
                    p[g].z = __expf(v.z - st.x) * st.y;
                    p[g].w = __expf(v.w - st.x) * st.y;
                } else {
                    int c0 = k0 + cs + g * 4;
                    p[g].x = (c0 + 0 <= rowG) ? __expf(v.x - st.x) * st.y : 0.f;
                    p[g].y = (c0 + 1 <= rowG) ? __expf(v.y - st.x) * st.y : 0.f;
                    p[g].z = (c0 + 2 <= rowG) ? __expf(v.z - st.x) * st.y : 0.f;
                    p[g].w = (c0 + 3 <= rowG) ? __expf(v.w - st.x) * st.y : 0.f;
                }
                __stcs((float4*)&P[(size_t)rowG * Ll + k0 + cs + g * 4], p[g]);
            }
            uint2 h0, l0, h1, l1, h2, l2, h3, l3;
            split_f4(p[0], h0, l0);
            split_f4(p[1], h1, l1);
            split_f4(p[2], h2, l2);
            split_f4(p[3], h3, l3);
            *(uint4*)&AhS[row * 40 + cs] = make_uint4(h0.x, h0.y, h1.x, h1.y);
            *(uint4*)&AhS[row * 40 + cs + 8] = make_uint4(h2.x, h2.y, h3.x, h3.y);
            *(uint4*)&AlS[row * 40 + cs] = make_uint4(l0.x, l0.y, l1.x, l1.y);
            *(uint4*)&AlS[row * 40 + cs + 8] = make_uint4(l2.x, l2.y, l3.x, l3.y);
        }

        if (ck + 1 < NK) {
            av_prefetch(sb, cur ^ 1, (ck + 1) * 32, P, Vh, Vl, vB,
                        rowG, row, cs, krow, cseg);
            CP_COMMIT();
        }
        __syncthreads();

        uint32_t vhB = sb + 57344 + cur * 9216;
        #pragma unroll
        for (int kk = 0; kk < 2; kk++) {
            uint32_t afh[2][4], afl[2][4];
            #pragma unroll
            for (int i = 0; i < 2; i++) {
                ldsm_x4(sb + 36864 + aoff + kk * 32 + i * 1280,
                        afh[i][0], afh[i][1], afh[i][2], afh[i][3]);
                ldsm_x4(sb + 47104 + aoff + kk * 32 + i * 1280,
                        afl[i][0], afl[i][1], afl[i][2], afl[i][3]);
            }
            #pragma unroll
            for (int j = 0; j < 2; j++) {
                uint32_t bh0, bh1, bh2, bh3, bl0, bl1, bl2, bl3;
                ldsm_x4_t(vhB + boff + kk * 2304 + j * 32, bh0, bh1, bh2, bh3);
                ldsm_x4_t(vhB + 4608 + boff + kk * 2304 + j * 32, bl0, bl1, bl2, bl3);
                #pragma unroll
                for (int i = 0; i < 2; i++) {
                    mma_bf16(c[i][2 * j], afh[i], bh0, bh1);
                    mma_bf16(c[i][2 * j], afh[i], bl0, bl1);
                    mma_bf16(c[i][2 * j], afl[i], bh0, bh1);
                    mma_bf16(c[i][2 * j + 1], afh[i], bh2, bh3);
                    mma_bf16(c[i][2 * j + 1], afh[i], bl2, bl3);
                    mma_bf16(c[i][2 * j + 1], afl[i], bh2, bh3);
                }
            }
        }
    }

    int r = lane >> 2, cl2 = (lane & 3) * 2;
    #pragma unroll
    for (int i = 0; i < 2; i++) {
        int orow = rowBase + m0 + i * 16 + r;
        #pragma unroll
        for (int j = 0; j < 4; j++) {
            int col = n0 + j * 8 + cl2;
            size_t off0 = (size_t)(b * Ll + orow) * Dd + h * 64 + col;
            size_t off1 = (size_t)(b * Ll + orow + 8) * Dd + h * 64 + col;
            uint32_t hh, ll;
            pack_split2(c[i][j][0], c[i][j][1], hh, ll);
            *(uint32_t*)&Oh[off0] = hh;
            *(uint32_t*)&Ol[off0] = ll;
            pack_split2(c[i][j][2], c[i][j][3], hh, ll);
            *(uint32_t*)&Oh[off1] = hh;
            *(uint32_t*)&Ol[off1] = ll;
        }
    }
}

// ---------------- launch ----------------
extern "C" void kernel_launch(void* const* d_in, const int* in_sizes, int n_in,
                              void* d_out, int out_size)
{
    const float* x   = (const float*)d_in[0];
    const float* Wq  = (const float*)d_in[1];
    const float* bq  = (const float*)d_in[2];
    const float* Wk  = (const float*)d_in[3];
    const float* bk  = (const float*)d_in[4];
    const float* Wv  = (const float*)d_in[5];
    const float* bv  = (const float*)d_in[6];
    const float* Wo  = (const float*)d_in[7];
    const float* bo  = (const float*)d_in[8];
    const float* lsc = (const float*)d_in[9];
    const float* gsc = (const float*)d_in[10];

    float* out   = (float*)d_out;
    float* attnL = out + (size_t)MLEN * Dd;
    float* attnG = attnL + (size_t)Bb * LH * Ll * Ll;

    uint16_t *xh, *xl, *Wqh, *Wql, *Wkh, *Wkl, *Wvh, *Wvl, *Woh, *Wol;
    uint16_t *Qh, *Ql, *Kh, *Kl, *Vh, *Vl, *Ohp, *Olp;
    float2 *bst, *rstp;
    cudaGetSymbolAddress((void**)&xh, g_xh);   cudaGetSymbolAddress((void**)&xl, g_xl);
    cudaGetSymbolAddress((void**)&Wqh, g_Wqh); cudaGetSymbolAddress((void**)&Wql, g_Wql);
    cudaGetSymbolAddress((void**)&Wkh, g_Wkh); cudaGetSymbolAddress((void**)&Wkl, g_Wkl);
    cudaGetSymbolAddress((void**)&Wvh, g_Wvh); cudaGetSymbolAddress((void**)&Wvl, g_Wvl);
    cudaGetSymbolAddress((void**)&Woh, g_Woh); cudaGetSymbolAddress((void**)&Wol, g_Wol);
    cudaGetSymbolAddress((void**)&Qh, g_Qh);   cudaGetSymbolAddress((void**)&Ql, g_Ql);
    cudaGetSymbolAddress((void**)&Kh, g_Kh);   cudaGetSymbolAddress((void**)&Kl, g_Kl);
    cudaGetSymbolAddress((void**)&Vh, g_Vh);   cudaGetSymbolAddress((void**)&Vl, g_Vl);
    cudaGetSymbolAddress((void**)&Ohp, g_Oh);  cudaGetSymbolAddress((void**)&Olp, g_Ol);
    cudaGetSymbolAddress((void**)&bst, g_bstats);
    cudaGetSymbolAddress((void**)&rstp, g_rstats);

    cudaFuncSetAttribute(scores_mma, cudaFuncAttributeMaxDynamicSharedMemorySize, SC_SMEM);
    cudaFuncSetAttribute(av_mma, cudaFuncAttributeMaxDynamicSharedMemorySize, AV_SMEM);
    cudaFuncSetAttribute(gemm_qkv, cudaFuncAttributeMaxDynamicSharedMemorySize, GEMM_SMEM);
    cudaFuncSetAttribute(gemm_out, cudaFuncAttributeMaxDynamicSharedMemorySize, GEMM_SMEM);

    int nx4 = MLEN * Dd / 4;
    int nw4 = Dd * Dd / 4;
    split_kernel<<<nx4 / 256, 256>>>((const float4*)x, (uint2*)xh, (uint2*)xl, nx4);
    split4_kernel<<<dim3(nw4 / 256, 1, 4), 256>>>(
        (const float4*)Wq, (uint2*)Wqh, (uint2*)Wql,
        (const float4*)Wk, (uint2*)Wkh, (uint2*)Wkl,
        (const float4*)Wv, (uint2*)Wvh, (uint2*)Wvl,
        (const float4*)Wo, (uint2*)Woh, (uint2*)Wol, nw4);

    gemm_qkv<<<dim3(8, 32, 3), 256, GEMM_SMEM>>>(xh, xl,
        Wqh, Wql, bq, Qh, Ql,
        Wkh, Wkl, bk, Kh, Kl,
        Wvh, Wvl, bv, Vh, Vl);

    scores_mma<<<dim3(16, 16, 32), 256, SC_SMEM>>>(Qh, Ql, Kh, Kl, lsc, gsc,
                                                   attnL, attnG, bst);
    reduce_stats<<<256, 256>>>(bst, rstp);
    av_mma<<<dim3(16, 32), 256, AV_SMEM>>>(attnL, attnG, Vh, Vl, rstp, Ohp, Olp);

    gemm_out<<<dim3(8, 32), 256, GEMM_SMEM>>>(Ohp, Olp, Woh, Wol, bo, out);
}

// round 14
// speedup vs baseline: 1.4846x; 1.0367x over previous
#include <cuda_runtime.h>
#include <cuda_bf16.h>
#include <math.h>
#include <stdint.h>

#define Bb 2
#define Ll 2048
#define Dd 1024
#define LH 8
#define MLEN (Bb * Ll)   // 4096

// ---------------- scratch ----------------
__device__ uint16_t g_xh[MLEN * Dd], g_xl[MLEN * Dd];
__device__ uint16_t g_Wqh[Dd * Dd], g_Wql[Dd * Dd];
__device__ uint16_t g_Wkh[Dd * Dd], g_Wkl[Dd * Dd];
__device__ uint16_t g_Wvh[Dd * Dd], g_Wvl[Dd * Dd];
__device__ uint16_t g_Woh[Dd * Dd], g_Wol[Dd * Dd];
__device__ uint16_t g_Qh[MLEN * Dd], g_Ql[MLEN * Dd];
__device__ uint16_t g_Kh[MLEN * Dd], g_Kl[MLEN * Dd];
__device__ uint16_t g_Vh[MLEN * Dd], g_Vl[MLEN * Dd];
__device__ uint16_t g_Oh[MLEN * Dd], g_Ol[MLEN * Dd];
__device__ float2 g_bstats[32 * 2048 * 32];
__device__ float2 g_rstats[32 * 2048];

// ---------------- helpers ----------------
__device__ __forceinline__ uint32_t smem_u32(const void* p) {
    return (uint32_t)__cvta_generic_to_shared(p);
}

__device__ __forceinline__ void cp_async16(uint32_t dst, const void* src) {
    asm volatile("cp.async.cg.shared.global [%0], [%1], 16;"
                 :: "r"(dst), "l"(src) : "memory");
}
#define CP_COMMIT() asm volatile("cp.async.commit_group;" ::: "memory")
#define CP_WAIT0()  asm volatile("cp.async.wait_group 0;" ::: "memory")
#define CP_WAIT1()  asm volatile("cp.async.wait_group 1;" ::: "memory")

__device__ __forceinline__ void pack_split2(float x0, float x1, uint32_t& h, uint32_t& l) {
    uint32_t u0 = __float_as_uint(x0), u1 = __float_as_uint(x1);
    h = (u0 >> 16) | (u1 & 0xffff0000u);
    float r0 = x0 - __uint_as_float(u0 & 0xffff0000u);
    float r1 = x1 - __uint_as_float(u1 & 0xffff0000u);
    asm("cvt.rn.bf16x2.f32 %0, %1, %2;" : "=r"(l) : "f"(r1), "f"(r0));
}
__device__ __forceinline__ void split_f4(float4 v, uint2& h, uint2& l) {
    pack_split2(v.x, v.y, h.x, l.x);
    pack_split2(v.z, v.w, h.y, l.y);
}

__device__ __forceinline__ void ldsm_x4(uint32_t addr, uint32_t& r0, uint32_t& r1,
                                        uint32_t& r2, uint32_t& r3) {
    asm volatile("ldmatrix.sync.aligned.m8n8.x4.shared.b16 {%0,%1,%2,%3}, [%4];"
                 : "=r"(r0), "=r"(r1), "=r"(r2), "=r"(r3) : "r"(addr));
}
__device__ __forceinline__ void ldsm_x4_t(uint32_t addr, uint32_t& r0, uint32_t& r1,
                                          uint32_t& r2, uint32_t& r3) {
    asm volatile("ldmatrix.sync.aligned.m8n8.x4.trans.shared.b16 {%0,%1,%2,%3}, [%4];"
                 : "=r"(r0), "=r"(r1), "=r"(r2), "=r"(r3) : "r"(addr));
}

__device__ __forceinline__ void mma_bf16(float* c, const uint32_t* a,
                                         uint32_t b0, uint32_t b1) {
    asm volatile(
        "mma.sync.aligned.m16n8k16.row.col.f32.bf16.bf16.f32 "
        "{%0,%1,%2,%3},{%4,%5,%6,%7},{%8,%9},{%0,%1,%2,%3};"
        : "+f"(c[0]), "+f"(c[1]), "+f"(c[2]), "+f"(c[3])
        : "r"(a[0]), "r"(a[1]), "r"(a[2]), "r"(a[3]), "r"(b0), "r"(b1));
}

// ---------------- zero-fill fully-masked local blocks (no data deps) ----------
__global__ void zerofill_kernel(float* __restrict__ attnL) {
    int lin = blockIdx.x;          // 0..1919 = 16 bh * 120 pairs
    int bh = lin / 120;            // local head index 0..15 (b*8+h)
    int p = lin % 120;
    // map p -> (rowIdx, colIdx) with colIdx > rowIdx in 16x16 block grid
    int r = 0, acc = 0;
    while (acc + (15 - r) <= p) { acc += 15 - r; r++; }
    int cIdx = r + 1 + (p - acc);
    float* dst = attnL + (size_t)bh * Ll * Ll + (size_t)(r * 128) * Ll + cIdx * 128;
    int tid = threadIdx.x;
    float4 z4 = make_float4(0.f, 0.f, 0.f, 0.f);
    #pragma unroll
    for (int i = 0; i < 16; i++) {
        int s = tid + i * 256;
        int row = s >> 5, c4 = s & 31;
        __stcs((float4*)&dst[(size_t)row * Ll + c4 * 4], z4);
    }
}

// ---------------- splits ----------------
__global__ void split_kernel(const float4* __restrict__ src, uint2* __restrict__ h,
                             uint2* __restrict__ l, int n4) {
    int i = blockIdx.x * 256 + threadIdx.x;
    if (i < n4) {
        uint2 hh, ll;
        split_f4(src[i], hh, ll);
        h[i] = hh;
        l[i] = ll;
    }
}

__global__ void split4_kernel(
    const float4* __restrict__ s0, uint2* h0, uint2* l0,
    const float4* __restrict__ s1, uint2* h1, uint2* l1,
    const float4* __restrict__ s2, uint2* h2, uint2* l2,
    const float4* __restrict__ s3, uint2* h3, uint2* l3, int n4)
{
    int z = blockIdx.z;
    const float4* s = (z == 0) ? s0 : (z == 1) ? s1 : (z == 2) ? s2 : s3;
    uint2* h = (z == 0) ? h0 : (z == 1) ? h1 : (z == 2) ? h2 : h3;
    uint2* l = (z == 0) ? l0 : (z == 1) ? l1 : (z == 2) ? l2 : l3;
    int i = blockIdx.x * 256 + threadIdx.x;
    if (i < n4) {
        uint2 hh, ll;
        split_f4(s[i], hh, ll);
        h[i] = hh;
        l[i] = ll;
    }
}

// ---------------- projection GEMM: 128x128, 3-stage cp.async ring -------------
#define PA 24
#define PB2 136
#define GSTAGE 20992
#define GEMM_SMEM (3 * GSTAGE)

__device__ __forceinline__ void gemm_stage3(
    const uint16_t* __restrict__ Ah, const uint16_t* __restrict__ Al,
    const uint16_t* __restrict__ Bh, const uint16_t* __restrict__ Bl,
    uint32_t sb, int buf, int k0, size_t aRow, int colBase,
    int ar, int asel, int brow, int bcol)
{
    const int N = 1024;
    uint32_t st = sb + (uint32_t)buf * GSTAGE;
    uint32_t aO = (uint32_t)(ar * PA + asel) * 2;
    uint32_t bO = (uint32_t)(brow * PB2 + bcol) * 2;
    cp_async16(st + aO, &Ah[aRow + k0 + asel]);
    cp_async16(st + 6144 + aO, &Al[aRow + k0 + asel]);
    cp_async16(st + 12288 + bO, &Bh[(size_t)(k0 + brow) * N + colBase + bcol]);
    cp_async16(st + 16640 + bO, &Bl[(size_t)(k0 + brow) * N + colBase + bcol]);
}

__device__ __forceinline__ void gemm_core(
    const uint16_t* __restrict__ Ah, const uint16_t* __restrict__ Al,
    const uint16_t* __restrict__ Bh, const uint16_t* __restrict__ Bl,
    const float* __restrict__ bias,
    uint16_t* __restrict__ outH, uint16_t* __restrict__ outL,
    float* __restrict__ outF, int mode, uint8_t* dsm)
{
    const int N = 1024, K = 1024;
    int tid = threadIdx.x, lane = tid & 31, wid = tid >> 5;
    int rowBase = blockIdx.y * 128, colBase = blockIdx.x * 128;
    int m0 = (wid >> 1) * 32, n0 = (wid & 1) * 64;

    int ar = tid >> 1, asel = (tid & 1) * 8;
    int brow = tid >> 4, bcol = (tid & 15) * 8;

    float c[2][8][4];
    #pragma unroll
    for (int i = 0; i < 2; i++)
        #pragma unroll
        for (int j = 0; j < 8; j++)
            #pragma unroll
            for (int q = 0; q < 4; q++) c[i][j][q] = 0.f;

    uint32_t sb = smem_u32(dsm);
    uint32_t aoff = (((m0 + (lane & 15)) * PA) + (lane >> 4) * 8) * 2;
    uint32_t boff = ((((lane & 7) + ((lane >> 3) & 1) * 8) * PB2) +
                     n0 + (lane >> 4) * 8) * 2;

    size_t aRow = (size_t)(rowBase + ar) * K;
    const int NK = K / 16;

    gemm_stage3(Ah, Al, Bh, Bl, sb, 0, 0, aRow, colBase, ar, asel, brow, bcol);
    CP_COMMIT();
    gemm_stage3(Ah, Al, Bh, Bl, sb, 1, 16, aRow, colBase, ar, asel, brow, bcol);
    CP_COMMIT();

    for (int ks = 0; ks < NK; ks++) {
        CP_WAIT1();
        __syncthreads();
        if (ks + 2 < NK) {
            gemm_stage3(Ah, Al, Bh, Bl, sb, (ks + 2) % 3, (ks + 2) * 16,
                        aRow, colBase, ar, asel, brow, bcol);
            CP_COMMIT();
        }
        uint32_t st = sb + (uint32_t)(ks % 3) * GSTAGE;
        uint32_t afh[2][4], afl[2][4];
        #pragma unroll
        for (int i = 0; i < 2; i++) {
            ldsm_x4(st + aoff + i * 768, afh[i][0], afh[i][1], afh[i][2], afh[i][3]);
            ldsm_x4(st + 6144 + aoff + i * 768, afl[i][0], afl[i][1], afl[i][2], afl[i][3]);
        }
        #pragma unroll
        for (int j = 0; j < 4; j++) {
            uint32_t bh0, bh1, bh2, bh3, bl0, bl1, bl2, bl3;
            ldsm_x4_t(st + 12288 + boff + j * 32, bh0, bh1, bh2, bh3);
            ldsm_x4_t(st + 16640 + boff + j * 32, bl0, bl1, bl2, bl3);
            #pragma unroll
            for (int i = 0; i < 2; i++) {
                mma_bf16(c[i][2 * j], afh[i], bh0, bh1);
                mma_bf16(c[i][2 * j], afh[i], bl0, bl1);
                mma_bf16(c[i][2 * j], afl[i], bh0, bh1);
                mma_bf16(c[i][2 * j + 1], afh[i], bh2, bh3);
                mma_bf16(c[i][2 * j + 1], afh[i], bl2, bl3);
                mma_bf16(c[i][2 * j + 1], afl[i], bh2, bh3);
            }
        }
    }

    int r = lane >> 2, cl2 = (lane & 3) * 2;
    #pragma unroll
    for (int i = 0; i < 2; i++) {
        int row = rowBase + m0 + i * 16 + r;
        #pragma unroll
        for (int j = 0; j < 8; j++) {
            int col = colBase + n0 + j * 8 + cl2;
            float b0 = bias[col], b1 = bias[col + 1];
            if (mode) {
                uint32_t hh, ll;
                pack_split2(c[i][j][0] + b0, c[i][j][1] + b1, hh, ll);
                *(uint32_t*)&outH[(size_t)row * N + col] = hh;
                *(uint32_t*)&outL[(size_t)row * N + col] = ll;
                pack_split2(c[i][j][2] + b0, c[i][j][3] + b1, hh, ll);
                *(uint32_t*)&outH[(size_t)(row + 8) * N + col] = hh;
                *(uint32_t*)&outL[(size_t)(row + 8) * N + col] = ll;
            } else {
                *(float2*)&outF[(size_t)row * N + col] =
                    make_float2(c[i][j][0] + b0, c[i][j][1] + b1);
                *(float2*)&outF[(size_t)(row + 8) * N + col] =
                    make_float2(c[i][j][2] + b0, c[i][j][3] + b1);
            }
        }
    }
}

__global__ __launch_bounds__(256, 2) void gemm_qkv(
    const uint16_t* __restrict__ Ah, const uint16_t* __restrict__ Al,
    const uint16_t* __restrict__ B0h, const uint16_t* __restrict__ B0l,
    const float* __restrict__ bias0, uint16_t* o0h, uint16_t* o0l,
    const uint16_t* __restrict__ B1h, const uint16_t* __restrict__ B1l,
    const float* __restrict__ bias1, uint16_t* o1h, uint16_t* o1l,
    const uint16_t* __restrict__ B2h, const uint16_t* __restrict__ B2l,
    const float* __restrict__ bias2, uint16_t* o2h, uint16_t* o2l)
{
    extern __shared__ __align__(16) uint8_t dsm8[];
    int z = blockIdx.z;
    const uint16_t* Bh = (z == 0) ? B0h : (z == 1) ? B1h : B2h;
    const uint16_t* Bl = (z == 0) ? B0l : (z == 1) ? B1l : B2l;
    const float* bias  = (z == 0) ? bias0 : (z == 1) ? bias1 : bias2;
    uint16_t* outH     = (z == 0) ? o0h : (z == 1) ? o1h : o2h;
    uint16_t* outL     = (z == 0) ? o0l : (z == 1) ? o1l : o2l;
    gemm_core(Ah, Al, Bh, Bl, bias, outH, outL, nullptr, 1, dsm8);
}

__global__ __launch_bounds__(256, 2) void gemm_out(
    const uint16_t* __restrict__ Ah, const uint16_t* __restrict__ Al,
    const uint16_t* __restrict__ Bh, const uint16_t* __restrict__ Bl,
    const float* __restrict__ bias, float* __restrict__ outF)
{
    extern __shared__ __align__(16) uint8_t dsm8[];
    gemm_core(Ah, Al, Bh, Bl, bias, nullptr, nullptr, outF, 0, dsm8);
}

// ---------------- scores: all K=64 resident, ONE sync -------------------------
#define SC_SMEM 73728
__global__ __launch_bounds__(256, 2) void scores_mma(
    const uint16_t* __restrict__ Qh, const uint16_t* __restrict__ Ql,
    const uint16_t* __restrict__ Kh, const uint16_t* __restrict__ Kl,
    const float* __restrict__ lsc, const float* __restrict__ gsc,
    float* __restrict__ attnL, float* __restrict__ attnG,
    float2* __restrict__ bstats)
{
    int bh = blockIdx.z;
    int b = bh >> 4, h = bh & 15;
    int rowBase = blockIdx.y * 128, colBase = blockIdx.x * 128;
    bool is_local = (h < LH);
    float* dst = is_local ? attnL + (size_t)(b * LH + h) * Ll * Ll
                          : attnG + (size_t)(b * LH + h - LH) * Ll * Ll;
    int tid = threadIdx.x;

    if (is_local && colBase > rowBase) return;   // zero-filled by zerofill_kernel
    bool diag = is_local && (colBase == rowBase);
    float scale = 0.125f * (is_local ? lsc[0] : gsc[0]);

    extern __shared__ __align__(16) uint16_t dsm[];
    uint16_t* sQh = dsm;
    uint16_t* sQl = dsm + 9216;
    uint16_t* sKh = dsm + 18432;
    uint16_t* sKl = dsm + 27648;

    int lane = tid & 31, wid = tid >> 5;
    int m0 = (wid >> 1) * 32, n0 = (wid & 1) * 64;

    #pragma unroll
    for (int i = 0; i < 4; i++) {
        int idx = tid + i * 256;
        int row = idx >> 3, cseg = (idx & 7) * 8;
        size_t gq = (size_t)(b * Ll + rowBase + row) * Dd + h * 64 + cseg;
        size_t gk = (size_t)(b * Ll + colBase + row) * Dd + h * 64 + cseg;
        *(uint4*)&sQh[row * 72 + cseg] = *(const uint4*)&Qh[gq];
        *(uint4*)&sQl[row * 72 + cseg] = *(const uint4*)&Ql[gq];
        *(uint4*)&sKh[row * 72 + cseg] = *(const uint4*)&Kh[gk];
        *(uint4*)&sKl[row * 72 + cseg] = *(const uint4*)&Kl[gk];
    }
    __syncthreads();

    float c[2][8][4];
    #pragma unroll
    for (int i = 0; i < 2; i++)
        #pragma unroll
        for (int j = 0; j < 8; j++)
            #pragma unroll
            for (int q = 0; q < 4; q++) c[i][j][q] = 0.f;

    uint32_t sQhA = smem_u32(sQh), sQlA = smem_u32(sQl);
    uint32_t sKhA = smem_u32(sKh), sKlA = smem_u32(sKl);
    uint32_t aoff = (((m0 + (lane & 15)) * 72) + (lane >> 4) * 8) * 2;
    uint32_t boff = (((n0 + (lane & 7) + (lane >> 4) * 8) * 72) +
                     ((lane >> 3) & 1) * 8) * 2;

    #pragma unroll
    for (int kk = 0; kk < 4; kk++) {
        uint32_t afh[2][4], afl[2][4];
        #pragma unroll
        for (int i = 0; i < 2; i++) {
            ldsm_x4(sQhA + aoff + i * 2304 + kk * 32,
                    afh[i][0], afh[i][1], afh[i][2], afh[i][3]);
            ldsm_x4(sQlA + aoff + i * 2304 + kk * 32,
                    afl[i][0], afl[i][1], afl[i][2], afl[i][3]);
        }
        #pragma unroll
        for (int j = 0; j < 4; j++) {
            uint32_t bh0, bh1, bh2, bh3, bl0, bl1, bl2, bl3;
            ldsm_x4(sKhA + boff + j * 2304 + kk * 32, bh0, bh1, bh2, bh3);
            ldsm_x4(sKlA + boff + j * 2304 + kk * 32, bl0, bl1, bl2, bl3);
            #pragma unroll
            for (int i = 0; i < 2; i++) {
                mma_bf16(c[i][2 * j], afh[i], bh0, bh1);
                mma_bf16(c[i][2 * j], afh[i], bl0, bl1);
                mma_bf16(c[i][2 * j], afl[i], bh0, bh1);
                mma_bf16(c[i][2 * j + 1], afh[i], bh2, bh3);
                mma_bf16(c[i][2 * j + 1], afh[i], bl2, bl3);
                mma_bf16(c[i][2 * j + 1], afl[i], bh2, bh3);
            }
        }
    }

    #pragma unroll
    for (int i = 0; i < 2; i++)
        #pragma unroll
        for (int j = 0; j < 8; j++)
            #pragma unroll
            for (int q = 0; q < 4; q++) c[i][j][q] *= scale;

    int r = lane >> 2, cl2 = (lane & 3) * 2;
    int ntile = (colBase + n0) >> 6;

    if (!diag) {
        #pragma unroll
        for (int i = 0; i < 2; i++) {
            #pragma unroll
            for (int half = 0; half < 2; half++) {
                int row = rowBase + m0 + i * 16 + r + half * 8;
                float m = -INFINITY;
                #pragma unroll
                for (int j = 0; j < 8; j++)
                    m = fmaxf(m, fmaxf(c[i][j][half * 2], c[i][j][half * 2 + 1]));
                m = fmaxf(m, __shfl_xor_sync(0xffffffffu, m, 1));
                m = fmaxf(m, __shfl_xor_sync(0xffffffffu, m, 2));
                float s = 0.f;
                #pragma unroll
                for (int j = 0; j < 8; j++) {
                    s += __expf(c[i][j][half * 2] - m);
                    s += __expf(c[i][j][half * 2 + 1] - m);
                }
                s += __shfl_xor_sync(0xffffffffu, s, 1);
                s += __shfl_xor_sync(0xffffffffu, s, 2);
                if ((lane & 3) == 0)
                    bstats[((size_t)bh * 2048 + row) * 32 + ntile] = make_float2(m, s);
                #pragma unroll
                for (int j = 0; j < 8; j++)
                    __stcs((float2*)&dst[(size_t)row * Ll + colBase + n0 + j * 8 + cl2],
                           make_float2(c[i][j][half * 2], c[i][j][half * 2 + 1]));
            }
        }
    } else {
        #pragma unroll
        for (int i = 0; i < 2; i++) {
            #pragma unroll
            for (int half = 0; half < 2; half++) {
                int row = rowBase + m0 + i * 16 + r + half * 8;
                float m = -INFINITY;
                #pragma unroll
                for (int j = 0; j < 8; j++) {
                    int col = colBase + n0 + j * 8 + cl2;
                    float v0 = c[i][j][half * 2], v1 = c[i][j][half * 2 + 1];
                    m = fmaxf(m, (col <= row) ? v0 : -INFINITY);
                    m = fmaxf(m, (col + 1 <= row) ? v1 : -INFINITY);
                }
                m = fmaxf(m, __shfl_xor_sync(0xffffffffu, m, 1));
                m = fmaxf(m, __shfl_xor_sync(0xffffffffu, m, 2));
                float s = 0.f;
                if (m > -1e30f) {
                    #pragma unroll
                    for (int j = 0; j < 8; j++) {
                        int col = colBase + n0 + j * 8 + cl2;
                        s += (col <= row) ? __expf(c[i][j][half * 2] - m) : 0.f;
                        s += (col + 1 <= row) ? __expf(c[i][j][half * 2 + 1] - m) : 0.f;
                    }
                }
                s += __shfl_xor_sync(0xffffffffu, s, 1);
                s += __shfl_xor_sync(0xffffffffu, s, 2);
                if ((lane & 3) == 0)
                    bstats[((size_t)bh * 2048 + row) * 32 + ntile] = make_float2(m, s);
                #pragma unroll
                for (int j = 0; j < 8; j++) {
                    int col = colBase + n0 + j * 8 + cl2;
                    float v0 = (col <= row) ? c[i][j][half * 2] : 0.f;
                    float v1 = (col + 1 <= row) ? c[i][j][half * 2 + 1] : 0.f;
                    __stcs((float2*)&dst[(size_t)row * Ll + col], make_float2(v0, v1));
                }
            }
        }
    }
}

// ---------------- reduce partial stats -> per-row (max, 1/Z) ----------------
__global__ void reduce_stats(const float2* __restrict__ bst, float2* __restrict__ rst) {
    int idx = blockIdx.x * 256 + threadIdx.x;
    int bh = idx >> 11, row = idx & 2047;
    bool is_local = (bh & 15) < LH;
    int jmax = is_local ? (row >> 6) : 31;
    const float2* p = &bst[(size_t)idx * 32];
    float m = -INFINITY;
    for (int j = 0; j <= jmax; j++) m = fmaxf(m, p[j].x);
    float Z = 0.f;
    for (int j = 0; j <= jmax; j++) {
        float2 v = p[j];
        if (v.x > -1e30f) Z += v.y * __expf(v.x - m);
    }
    rst[idx] = make_float2(m, 1.f / Z);
}

// ---------------- AV: chunk=32, cp.async pipelined rawS + V, LPT order --------
#define AV_SMEM 75776

__device__ __forceinline__ void av_prefetch(
    uint32_t sb, int buf, int k0,
    const float* __restrict__ P, const uint16_t* __restrict__ Vh,
    const uint16_t* __restrict__ Vl, size_t vB,
    int rowG, int row, int cs, int krow, int cseg)
{
    #pragma unroll
    for (int g = 0; g < 4; g++)
        cp_async16(sb + buf * 18432 + (row * 36 + cs + g * 4) * 4,
                   &P[(size_t)rowG * Ll + k0 + cs + g * 4]);
    uint32_t vdst = sb + 57344 + buf * 9216 + (krow * 72 + cseg) * 2;
    cp_async16(vdst, &Vh[vB + (size_t)(k0 + krow) * Dd + cseg]);
    cp_async16(vdst + 4608, &Vl[vB + (size_t)(k0 + krow) * Dd + cseg]);
}

__global__ __launch_bounds__(256, 2) void av_mma(
    float* attnL, float* attnG,
    const uint16_t* __restrict__ Vh, const uint16_t* __restrict__ Vl,
    const float2* __restrict__ rst,
    uint16_t* __restrict__ Oh, uint16_t* __restrict__ Ol)
{
    extern __shared__ __align__(16) uint8_t avs[];
    uint32_t sb = smem_u32(avs);

    int lin = blockIdx.y * 16 + blockIdx.x;
    int bh, rowIdx;
    if (lin < 256) {
        bh = ((lin >> 7) << 4) + 8 + ((lin >> 4) & 7);
        rowIdx = lin & 15;
    } else {
        int loc = lin - 256;
        rowIdx = 15 - (loc >> 4);
        int sub = loc & 15;
        bh = ((sub >> 3) << 4) + (sub & 7);
    }
    int b = bh >> 4, h = bh & 15;
    int rowBase = rowIdx * 128;
    bool is_local = (h < LH);

    float* P = is_local ? attnL + (size_t)(b * LH + h) * Ll * Ll
                        : attnG + (size_t)(b * LH + h - LH) * Ll * Ll;
    int NK = (is_local ? (rowBase + 128) : Ll) / 32;
    int maskC = is_local ? (rowBase >> 5) : (1 << 30);

    int tid = threadIdx.x, lane = tid & 31, wid = tid >> 5;
    int m0 = (wid >> 1) * 32, n0 = (wid & 1) * 32;

    int row = tid >> 1, cs = (tid & 1) * 16;
    int rowG = rowBase + row;
    float2 st = rst[(size_t)bh * 2048 + rowG];
    int krow = tid >> 3, cseg = (tid & 7) * 8;
    size_t vB = (size_t)(b * Ll) * Dd + h * 64;

    float c[2][4][4];
    #pragma unroll
    for (int i = 0; i < 2; i++)
        #pragma unroll
        for (int j = 0; j < 4; j++)
            #pragma unroll
            for (int q = 0; q < 4; q++) c[i][j][q] = 0.f;

    uint32_t aoff = (((m0 + (lane & 15)) * 40) + (lane >> 4) * 8) * 2;
    uint32_t boff = ((((lane & 7) + ((lane >> 3) & 1) * 8) * 72) +
                     n0 + (lane >> 4) * 8) * 2;

    uint16_t* AhS = (uint16_t*)(avs + 36864);
    uint16_t* AlS = (uint16_t*)(avs + 47104);

    av_prefetch(sb, 0, 0, P, Vh, Vl, vB, rowG, row, cs, krow, cseg);
    CP_COMMIT();

    for (int ck = 0; ck < NK; ck++) {
        int cur = ck & 1;
        int k0 = ck * 32;
        CP_WAIT0();
        __syncthreads();

        {
            const float* rawS = (const float*)(avs + cur * 18432);
            bool needMask = (ck >= maskC);
            float4 p[4];
            #pragma unroll
            for (int g = 0; g < 4; g++) {
                float4 v = *(const float4*)&rawS[row * 36 + cs + g * 4];
                if (!needMask) {
                    p[g].x = __expf(v.x - st.x) * st.y;
                    p[g].y = __expf(v.y - st.x) * st.y;
                    p[g].z = __expf(v.z - st.x) * st.y;
                    p[g].w = __expf(v.w - st.x) * st.y;
                } else {
                    int c0 = k0 + cs + g * 4;
                    p[g].x = (c0 + 0 <= rowG) ? __expf(v.x - st.x) * st.y : 0.f;
                    p[g].y = (c0 + 1 <= rowG) ? __expf(v.y - st.x) * st.y : 0.f;
                    p[g].z = (c0 + 2 <= rowG) ? __expf(v.z - st.x) * st.y : 0.f;
                    p[g].w = (c0 + 3 <= rowG) ? __expf(v.w - st.x) * st.y : 0.f;
                }
                __stcs((float4*)&P[(size_t)rowG * Ll + k0 + cs + g * 4], p[g]);
            }
            uint2 h0, l0, h1, l1, h2, l2, h3, l3;
            split_f4(p[0], h0, l0);
            split_f4(p[1], h1, l1);
            split_f4(p[2], h2, l2);
            split_f4(p[3], h3, l3);
            *(uint4*)&AhS[row * 40 + cs] = make_uint4(h0.x, h0.y, h1.x, h1.y);
            *(uint4*)&AhS[row * 40 + cs + 8] = make_uint4(h2.x, h2.y, h3.x, h3.y);
            *(uint4*)&AlS[row * 40 + cs] = make_uint4(l0.x, l0.y, l1.x, l1.y);
            *(uint4*)&AlS[row * 40 + cs + 8] = make_uint4(l2.x, l2.y, l3.x, l3.y);
        }

        if (ck + 1 < NK) {
            av_prefetch(sb, cur ^ 1, (ck + 1) * 32, P, Vh, Vl, vB,
                        rowG, row, cs, krow, cseg);
            CP_COMMIT();
        }
        __syncthreads();

        uint32_t vhB = sb + 57344 + cur * 9216;
        #pragma unroll
        for (int kk = 0; kk < 2; kk++) {
            uint32_t afh[2][4], afl[2][4];
            #pragma unroll
            for (int i = 0; i < 2; i++) {
                ldsm_x4(sb + 36864 + aoff + kk * 32 + i * 1280,
                        afh[i][0], afh[i][1], afh[i][2], afh[i][3]);
                ldsm_x4(sb + 47104 + aoff + kk * 32 + i * 1280,
                        afl[i][0], afl[i][1], afl[i][2], afl[i][3]);
            }
            #pragma unroll
            for (int j = 0; j < 2; j++) {
                uint32_t bh0, bh1, bh2, bh3, bl0, bl1, bl2, bl3;
                ldsm_x4_t(vhB + boff + kk * 2304 + j * 32, bh0, bh1, bh2, bh3);
                ldsm_x4_t(vhB + 4608 + boff + kk * 2304 + j * 32, bl0, bl1, bl2, bl3);
                #pragma unroll
                for (int i = 0; i < 2; i++) {
                    mma_bf16(c[i][2 * j], afh[i], bh0, bh1);
                    mma_bf16(c[i][2 * j], afh[i], bl0, bl1);
                    mma_bf16(c[i][2 * j], afl[i], bh0, bh1);
                    mma_bf16(c[i][2 * j + 1], afh[i], bh2, bh3);
                    mma_bf16(c[i][2 * j + 1], afh[i], bl2, bl3);
                    mma_bf16(c[i][2 * j + 1], afl[i], bh2, bh3);
                }
            }
        }
    }

    int r = lane >> 2, cl2 = (lane & 3) * 2;
    #pragma unroll
    for (int i = 0; i < 2; i++) {
        int orow = rowBase + m0 + i * 16 + r;
        #pragma unroll
        for (int j = 0; j < 4; j++) {
            int col = n0 + j * 8 + cl2;
            size_t off0 = (size_t)(b * Ll + orow) * Dd + h * 64 + col;
            size_t off1 = (size_t)(b * Ll + orow + 8) * Dd + h * 64 + col;
            uint32_t hh, ll;
            pack_split2(c[i][j][0], c[i][j][1], hh, ll);
            *(uint32_t*)&Oh[off0] = hh;
            *(uint32_t*)&Ol[off0] = ll;
            pack_split2(c[i][j][2], c[i][j][3], hh, ll);
            *(uint32_t*)&Oh[off1] = hh;
            *(uint32_t*)&Ol[off1] = ll;
        }
    }
}

// ---------------- launch ----------------
extern "C" void kernel_launch(void* const* d_in, const int* in_sizes, int n_in,
                              void* d_out, int out_size)
{
    const float* x   = (const float*)d_in[0];
    const float* Wq  = (const float*)d_in[1];
    const float* bq  = (const float*)d_in[2];
    const float* Wk  = (const float*)d_in[3];
    const float* bk  = (const float*)d_in[4];
    const float* Wv  = (const float*)d_in[5];
    const float* bv  = (const float*)d_in[6];
    const float* Wo  = (const float*)d_in[7];
    const float* bo  = (const float*)d_in[8];
    const float* lsc = (const float*)d_in[9];
    const float* gsc = (const float*)d_in[10];

    float* out   = (float*)d_out;
    float* attnL = out + (size_t)MLEN * Dd;
    float* attnG = attnL + (size_t)Bb * LH * Ll * Ll;

    uint16_t *xh, *xl, *Wqh, *Wql, *Wkh, *Wkl, *Wvh, *Wvl, *Woh, *Wol;
    uint16_t *Qh, *Ql, *Kh, *Kl, *Vh, *Vl, *Ohp, *Olp;
    float2 *bst, *rstp;
    cudaGetSymbolAddress((void**)&xh, g_xh);   cudaGetSymbolAddress((void**)&xl, g_xl);
    cudaGetSymbolAddress((void**)&Wqh, g_Wqh); cudaGetSymbolAddress((void**)&Wql, g_Wql);
    cudaGetSymbolAddress((void**)&Wkh, g_Wkh); cudaGetSymbolAddress((void**)&Wkl, g_Wkl);
    cudaGetSymbolAddress((void**)&Wvh, g_Wvh); cudaGetSymbolAddress((void**)&Wvl, g_Wvl);
    cudaGetSymbolAddress((void**)&Woh, g_Woh); cudaGetSymbolAddress((void**)&Wol, g_Wol);
    cudaGetSymbolAddress((void**)&Qh, g_Qh);   cudaGetSymbolAddress((void**)&Ql, g_Ql);
    cudaGetSymbolAddress((void**)&Kh, g_Kh);   cudaGetSymbolAddress((void**)&Kl, g_Kl);
    cudaGetSymbolAddress((void**)&Vh, g_Vh);   cudaGetSymbolAddress((void**)&Vl, g_Vl);
    cudaGetSymbolAddress((void**)&Ohp, g_Oh);  cudaGetSymbolAddress((void**)&Olp, g_Ol);
    cudaGetSymbolAddress((void**)&bst, g_bstats);
    cudaGetSymbolAddress((void**)&rstp, g_rstats);

    cudaFuncSetAttribute(scores_mma, cudaFuncAttributeMaxDynamicSharedMemorySize, SC_SMEM);
    cudaFuncSetAttribute(av_mma, cudaFuncAttributeMaxDynamicSharedMemorySize, AV_SMEM);
    cudaFuncSetAttribute(gemm_qkv, cudaFuncAttributeMaxDynamicSharedMemorySize, GEMM_SMEM);
    cudaFuncSetAttribute(gemm_out, cudaFuncAttributeMaxDynamicSharedMemorySize, GEMM_SMEM);

    static cudaStream_t s2 = nullptr;
    static cudaEvent_t evFork = nullptr, evSplit = nullptr, evV = nullptr;
    if (!s2) {
        cudaStreamCreateWithFlags(&s2, cudaStreamNonBlocking);
        cudaEventCreateWithFlags(&evFork, cudaEventDisableTiming);
        cudaEventCreateWithFlags(&evSplit, cudaEventDisableTiming);
        cudaEventCreateWithFlags(&evV, cudaEventDisableTiming);
    }

    int nx4 = MLEN * Dd / 4;
    int nw4 = Dd * Dd / 4;

    // fork s2 into the capture graph; zerofill has no data deps
    cudaEventRecord(evFork, 0);
    cudaStreamWaitEvent(s2, evFork, 0);
    zerofill_kernel<<<1920, 256, 0, s2>>>(attnL);

    split_kernel<<<nx4 / 256, 256>>>((const float4*)x, (uint2*)xh, (uint2*)xl, nx4);
    split4_kernel<<<dim3(nw4 / 256, 1, 4), 256>>>(
        (const float4*)Wq, (uint2*)Wqh, (uint2*)Wql,
        (const float4*)Wk, (uint2*)Wkh, (uint2*)Wkl,
        (const float4*)Wv, (uint2*)Wvh, (uint2*)Wvl,
        (const float4*)Wo, (uint2*)Woh, (uint2*)Wol, nw4);
    cudaEventRecord(evSplit, 0);
    cudaStreamWaitEvent(s2, evSplit, 0);

    // V-projection on s2 (only needed by av_mma)
    gemm_qkv<<<dim3(8, 32, 1), 256, GEMM_SMEM, s2>>>(xh, xl,
        Wvh, Wvl, bv, Vh, Vl,
        Wvh, Wvl, bv, Vh, Vl,
        Wvh, Wvl, bv, Vh, Vl);
    cudaEventRecord(evV, s2);

    // Q,K projections on main; scores depends only on these
    gemm_qkv<<<dim3(8, 32, 2), 256, GEMM_SMEM>>>(xh, xl,
        Wqh, Wql, bq, Qh, Ql,
        Wkh, Wkl, bk, Kh, Kl,
        Wkh, Wkl, bk, Kh, Kl);

    scores_mma<<<dim3(16, 16, 32), 256, SC_SMEM>>>(Qh, Ql, Kh, Kl, lsc, gsc,
                                                   attnL, attnG, bst);
    reduce_stats<<<256, 256>>>(bst, rstp);

    cudaStreamWaitEvent(0, evV, 0);   // join V (and zerofill) before AV
    av_mma<<<dim3(16, 32), 256, AV_SMEM>>>(attnL, attnG, Vh, Vl, rstp, Ohp, Olp);

    gemm_out<<<dim3(8, 32), 256, GEMM_SMEM>>>(Ohp, Olp, Woh, Wol, bo, out);
}